// round 14
// baseline (speedup 1.0000x reference)
#include <cuda_runtime.h>
#include <cuda_fp16.h>
#include <math.h>
#include <stdint.h>

// ----------------------------------------------------------------------------
// Problem constants
// ----------------------------------------------------------------------------
#define BSZ   16
#define HIMG  64
#define WIMG  64
#define CH    256
#define NTOK  (BSZ*HIMG*WIMG)       // 65536
#define NHEAD 8
#define HS    32
#define PP    16
#define NDTOK (BSZ*PP*PP)           // 4096

// fp16 weight slots ([N][K]): 12 attn + 3 axial + sq1 + sq2
#define WF_ATTN 0
#define WF_AX   (12*65536)
#define WF_SQ1  (15*65536)
#define WF_SQ2  (16*65536)
#define WFTOT   (17*65536)

// ----------------------------------------------------------------------------
// Scratch
// ----------------------------------------------------------------------------
__device__ __half g_QKV[9][NTOK*CH];
__device__ __half g_CTX[3][NTOK*CH];
__device__ __half g_S[3][NTOK*CH];
__device__ __half g_xf[NTOK*CH];
__device__ __half g_Wf[WFTOT];
__device__ __half g_xdlf[NDTOK*CH];
__device__ __half g_xgh[NDTOK*CH];
__device__ float  g_y[NDTOK*CH];
__device__ float  g_zerob[CH];
__device__ float  g_t9[NTOK*9];
__device__ float  g_edge[NTOK];
__device__ float  g_wts[NTOK*3];
__device__ float  g_aQ[NDTOK*CH];
__device__ float  g_aK[NDTOK*CH];
__device__ float  g_aV[NDTOK*CH];
__device__ float  g_xg32[NDTOK*CH];

// ----------------------------------------------------------------------------
// PTX helpers
// ----------------------------------------------------------------------------
__device__ __forceinline__ uint32_t smem_u32(const void* p) {
    uint32_t a;
    asm("{ .reg .u64 t; cvta.to.shared.u64 t, %1; cvt.u32.u64 %0, t; }"
        : "=r"(a) : "l"(p));
    return a;
}
__device__ __forceinline__ void ldsm4(uint32_t* r, uint32_t addr) {
    asm volatile("ldmatrix.sync.aligned.m8n8.x4.shared.b16 {%0,%1,%2,%3}, [%4];"
                 : "=r"(r[0]), "=r"(r[1]), "=r"(r[2]), "=r"(r[3]) : "r"(addr));
}
__device__ __forceinline__ void mma_f16(float* d, const uint32_t* a,
                                        uint32_t b0, uint32_t b1) {
    asm volatile("mma.sync.aligned.m16n8k16.row.col.f32.f16.f16.f32 "
                 "{%0,%1,%2,%3}, {%4,%5,%6,%7}, {%8,%9}, {%0,%1,%2,%3};"
                 : "+f"(d[0]), "+f"(d[1]), "+f"(d[2]), "+f"(d[3])
                 : "r"(a[0]), "r"(a[1]), "r"(a[2]), "r"(a[3]), "r"(b0), "r"(b1));
}
#define CP16(dst, src) \
    asm volatile("cp.async.cg.shared.global [%0], [%1], 16;" :: "r"(dst), "l"(src))
#define CP_COMMIT() asm volatile("cp.async.commit_group;" ::: "memory")
#define CP_WAIT0()  asm volatile("cp.async.wait_group 0;" ::: "memory")

__device__ __forceinline__ void u4_to_f4x2(uint4 r, float4& a, float4& b) {
    __half2 h0 = *(__half2*)&r.x, h1 = *(__half2*)&r.y;
    __half2 h2 = *(__half2*)&r.z, h3 = *(__half2*)&r.w;
    float2 f0 = __half22float2(h0), f1 = __half22float2(h1);
    float2 f2 = __half22float2(h2), f3 = __half22float2(h3);
    a = make_float4(f0.x, f0.y, f1.x, f1.y);
    b = make_float4(f2.x, f2.y, f3.x, f3.y);
}
__device__ __forceinline__ uint4 f4x2_to_u4(float4 a, float4 b) {
    __half2 h0 = __floats2half2_rn(a.x, a.y), h1 = __floats2half2_rn(a.z, a.w);
    __half2 h2 = __floats2half2_rn(b.x, b.y), h3 = __floats2half2_rn(b.z, b.w);
    uint4 r;
    r.x = *(uint32_t*)&h0; r.y = *(uint32_t*)&h1;
    r.z = *(uint32_t*)&h2; r.w = *(uint32_t*)&h3;
    return r;
}
__device__ __forceinline__ void store2(float* p, float a, float b) {
    *(float2*)p = make_float2(a, b);
}
__device__ __forceinline__ void store2(__half* p, float a, float b) {
    *(__half2*)p = __floats2half2_rn(a, b);
}

// ----------------------------------------------------------------------------
// fp16 GEMM (round-7 proven config)
// ----------------------------------------------------------------------------
template<typename OT> struct TileT {
    const __half *a, *b;
    const float* bias;
    OT* out;
};
template<typename OT, int NM> struct TilesT { TileT<OT> t[NM]; };

#define SMH_A   0
#define SMH_B   10240
#define SMH_BUF 20480
#define GEMM_SMEM (2*SMH_BUF)

template<typename OT>
__device__ __forceinline__ void load_chunkh(
    uint32_t sbase, const TileT<OT>& e, int K, int row0, int col0, int k0, int t)
{
    const int lrow = t >> 1;
    const int lseg = (t & 1) * 16;
    const uint32_t doff = (uint32_t)(lrow * 80 + lseg * 2);
    const __half* s = e.a + (size_t)(row0 + lrow) * K + k0 + lseg;
    CP16(sbase + SMH_A + doff,      s);
    CP16(sbase + SMH_A + doff + 16, s + 8);
    s = e.b + (size_t)(col0 + lrow) * K + k0 + lseg;
    CP16(sbase + SMH_B + doff,      s);
    CP16(sbase + SMH_B + doff + 16, s + 8);
}

template<typename OT, int NM>
__global__ __launch_bounds__(256)
void gemm_h(TilesT<OT, NM> T, int K)
{
    extern __shared__ char sm[];
    const uint32_t sb0 = smem_u32(sm);

    const int t = threadIdx.x;
    const int wid = t >> 5, lane = t & 31;
    const TileT<OT> e = T.t[blockIdx.x >> 1];
    const int col0 = (blockIdx.x & 1) * 128;
    const int row0 = blockIdx.y * 128;
    const int mw = wid & 3;
    const int nw = wid >> 2;
    const int NC = K >> 5;

    float acc[2][8][4];
    #pragma unroll
    for (int i = 0; i < 2; i++)
        #pragma unroll
        for (int j = 0; j < 8; j++)
            #pragma unroll
            for (int q = 0; q < 4; q++) acc[i][j][q] = 0.f;

    load_chunkh(sb0, e, K, row0, col0, 0, t);
    CP_COMMIT();

    const uint32_t a_off[2] = {
        (uint32_t)((mw*32 + 0*16 + (lane & 15)) * 80),
        (uint32_t)((mw*32 + 1*16 + (lane & 15)) * 80)
    };
    const uint32_t a_col = (uint32_t)(((lane >> 4) << 3) * 2);
    uint32_t b_off[4];
    #pragma unroll
    for (int j = 0; j < 4; j++)
        b_off[j] = (uint32_t)((nw*64 + j*16 + (lane & 7) + ((lane >> 4) << 3)) * 80);
    const uint32_t b_col = (uint32_t)((((lane >> 3) & 1) << 3) * 2);

    for (int c = 0; c < NC; c++) {
        CP_WAIT0();
        __syncthreads();
        if (c + 1 < NC) {
            load_chunkh(sb0 + (uint32_t)((c + 1) & 1) * SMH_BUF, e, K, row0, col0,
                        (c + 1) << 5, t);
            CP_COMMIT();
        }
        const uint32_t bb = sb0 + (uint32_t)(c & 1) * SMH_BUF;

        #pragma unroll
        for (int ks = 0; ks < 2; ks++) {
            const uint32_t kc = (uint32_t)(ks * 32);
            uint32_t af[2][4], bf[4][4];
            #pragma unroll
            for (int mt = 0; mt < 2; mt++)
                ldsm4(af[mt], bb + SMH_A + a_off[mt] + kc + a_col);
            #pragma unroll
            for (int j = 0; j < 4; j++)
                ldsm4(bf[j], bb + SMH_B + b_off[j] + kc + b_col);
            #pragma unroll
            for (int mt = 0; mt < 2; mt++)
                #pragma unroll
                for (int j = 0; j < 4; j++) {
                    mma_f16(acc[mt][2*j],     af[mt], bf[j][0], bf[j][1]);
                    mma_f16(acc[mt][2*j + 1], af[mt], bf[j][2], bf[j][3]);
                }
        }
        __syncthreads();
    }

    #pragma unroll
    for (int mt = 0; mt < 2; mt++) {
        const int r_ = row0 + mw*32 + mt*16 + (lane >> 2);
        #pragma unroll
        for (int j = 0; j < 8; j++) {
            const int c_ = col0 + nw*64 + j*8 + (lane & 3)*2;
            const float b0 = e.bias[c_], b1 = e.bias[c_ + 1];
            store2(&e.out[(size_t)r_ * 256 + c_],       acc[mt][j][0] + b0, acc[mt][j][1] + b1);
            store2(&e.out[(size_t)(r_ + 8) * 256 + c_], acc[mt][j][2] + b0, acc[mt][j][3] + b1);
        }
    }
}

// ----------------------------------------------------------------------------
// Final GEMM with fused blend + bilinear-up epilogue:
//   A[pix,k] = w0*S0 + w1*S1 + w2*S2  (computed in the A-loader, fp16)
//   out = A @ W2^T + sq_b + bilerp(y)
// ----------------------------------------------------------------------------
__global__ __launch_bounds__(256)
void gemm_upz(const __half* __restrict__ S0, const __half* __restrict__ S1,
              const __half* __restrict__ S2, const float* __restrict__ wts,
              const __half* __restrict__ B, const float* __restrict__ bias,
              const float* __restrict__ y, float* __restrict__ Cm)
{
    extern __shared__ char sm[];
    const uint32_t sb0 = smem_u32(sm);

    const int t = threadIdx.x;
    const int wid = t >> 5, lane = t & 31;
    const int col0 = (blockIdx.x & 1) * 128;
    const int row0 = blockIdx.y * 128;
    const int mw = wid & 3;
    const int nw = wid >> 2;
    const int NC = 8;
    const int K = 256;

    const int lrow = t >> 1;
    const int lseg = (t & 1) * 16;
    const uint32_t doff = (uint32_t)(lrow * 80 + lseg * 2);
    const int apix = row0 + lrow;
    const float w0 = wts[apix*3 + 0], w1 = wts[apix*3 + 1], w2 = wts[apix*3 + 2];

    auto loadA = [&](uint32_t bbase, int k0) {
        const size_t off = (size_t)apix * 256 + k0 + lseg;
        const uint4* p0 = (const uint4*)(S0 + off);
        const uint4* p1 = (const uint4*)(S1 + off);
        const uint4* p2 = (const uint4*)(S2 + off);
        #pragma unroll
        for (int h = 0; h < 2; h++) {
            float4 a0, a1, b0, b1, c0, c1;
            u4_to_f4x2(p0[h], a0, a1);
            u4_to_f4x2(p1[h], b0, b1);
            u4_to_f4x2(p2[h], c0, c1);
            float4 r0, r1;
            r0.x = w0*a0.x + w1*b0.x + w2*c0.x;
            r0.y = w0*a0.y + w1*b0.y + w2*c0.y;
            r0.z = w0*a0.z + w1*b0.z + w2*c0.z;
            r0.w = w0*a0.w + w1*b0.w + w2*c0.w;
            r1.x = w0*a1.x + w1*b1.x + w2*c1.x;
            r1.y = w0*a1.y + w1*b1.y + w2*c1.y;
            r1.z = w0*a1.z + w1*b1.z + w2*c1.z;
            r1.w = w0*a1.w + w1*b1.w + w2*c1.w;
            *(uint4*)(sm + (bbase - sb0) + SMH_A + doff + h*16) = f4x2_to_u4(r0, r1);
        }
    };
    auto loadB = [&](uint32_t bbase, int k0) {
        const __half* s = B + (size_t)(col0 + lrow) * K + k0 + lseg;
        CP16(bbase + SMH_B + doff,      s);
        CP16(bbase + SMH_B + doff + 16, s + 8);
    };

    float acc[2][8][4];
    #pragma unroll
    for (int i = 0; i < 2; i++)
        #pragma unroll
        for (int j = 0; j < 8; j++)
            #pragma unroll
            for (int q = 0; q < 4; q++) acc[i][j][q] = 0.f;

    loadA(sb0, 0);
    loadB(sb0, 0);
    CP_COMMIT();

    const uint32_t a_off[2] = {
        (uint32_t)((mw*32 + 0*16 + (lane & 15)) * 80),
        (uint32_t)((mw*32 + 1*16 + (lane & 15)) * 80)
    };
    const uint32_t a_col = (uint32_t)(((lane >> 4) << 3) * 2);
    uint32_t b_off[4];
    #pragma unroll
    for (int j = 0; j < 4; j++)
        b_off[j] = (uint32_t)((nw*64 + j*16 + (lane & 7) + ((lane >> 4) << 3)) * 80);
    const uint32_t b_col = (uint32_t)((((lane >> 3) & 1) << 3) * 2);

    for (int c = 0; c < NC; c++) {
        CP_WAIT0();
        __syncthreads();
        if (c + 1 < NC) {
            const uint32_t nb = sb0 + (uint32_t)((c + 1) & 1) * SMH_BUF;
            loadA(nb, (c + 1) << 5);
            loadB(nb, (c + 1) << 5);
            CP_COMMIT();
        }
        const uint32_t bb = sb0 + (uint32_t)(c & 1) * SMH_BUF;

        #pragma unroll
        for (int ks = 0; ks < 2; ks++) {
            const uint32_t kc = (uint32_t)(ks * 32);
            uint32_t af[2][4], bf[4][4];
            #pragma unroll
            for (int mt = 0; mt < 2; mt++)
                ldsm4(af[mt], bb + SMH_A + a_off[mt] + kc + a_col);
            #pragma unroll
            for (int j = 0; j < 4; j++)
                ldsm4(bf[j], bb + SMH_B + b_off[j] + kc + b_col);
            #pragma unroll
            for (int mt = 0; mt < 2; mt++)
                #pragma unroll
                for (int j = 0; j < 4; j++) {
                    mma_f16(acc[mt][2*j],     af[mt], bf[j][0], bf[j][1]);
                    mma_f16(acc[mt][2*j + 1], af[mt], bf[j][2], bf[j][3]);
                }
        }
        __syncthreads();
    }

    const float scl = 15.f / 63.f;
    #pragma unroll
    for (int mt = 0; mt < 2; mt++) {
        #pragma unroll
        for (int hh = 0; hh < 2; hh++) {
            const int pix = row0 + mw*32 + mt*16 + (lane >> 2) + hh*8;
            const int bimg = pix >> 12, yy = (pix >> 6) & 63, xx = pix & 63;
            float pr = yy * scl;
            int r0 = (int)floorf(pr);
            float tr = pr - (float)r0;
            int r1 = min(r0 + 1, 15);
            float pc = xx * scl;
            int c0i = (int)floorf(pc);
            float tc = pc - (float)c0i;
            int c1i = min(c0i + 1, 15);
            const float* yb = y + (size_t)bimg * 256 * CH;
            const float* y00 = yb + (r0*16 + c0i)*CH;
            const float* y01 = yb + (r0*16 + c1i)*CH;
            const float* y10 = yb + (r1*16 + c0i)*CH;
            const float* y11 = yb + (r1*16 + c1i)*CH;
            const float w00 = (1.f-tr)*(1.f-tc), w01 = (1.f-tr)*tc;
            const float w10 = tr*(1.f-tc),       w11 = tr*tc;
            #pragma unroll
            for (int j = 0; j < 8; j++) {
                const int c_ = col0 + nw*64 + j*8 + (lane & 3)*2;
                float2 v00 = *(const float2*)&y00[c_];
                float2 v01 = *(const float2*)&y01[c_];
                float2 v10 = *(const float2*)&y10[c_];
                float2 v11 = *(const float2*)&y11[c_];
                float up0 = w00*v00.x + w01*v01.x + w10*v10.x + w11*v11.x;
                float up1 = w00*v00.y + w01*v01.y + w10*v10.y + w11*v11.y;
                const float a0 = acc[mt][j][hh*2 + 0], a1 = acc[mt][j][hh*2 + 1];
                store2(&Cm[(size_t)pix * 256 + c_],
                       a0 + bias[c_] + up0, a1 + bias[c_ + 1] + up1);
            }
        }
    }
}

// ----------------------------------------------------------------------------
// Weight conversion + x conversion
// ----------------------------------------------------------------------------
__global__ void convw_all(const float* __restrict__ attn_w,
                          const float* __restrict__ ax_w,
                          const float* __restrict__ sq_w,
                          __half* __restrict__ Wf)
{
    const int idx = blockIdx.x * 256 + threadIdx.x;   // 17*65536
    const int m = idx >> 16, r = idx & 65535;
    if (m < 15) {
        const int k = r >> 8, n = r & 255;
        const float w = (m < 12) ? attn_w[idx] : ax_w[(m - 12)*65536 + r];
        Wf[((size_t)m << 16) + (n << 8) + k] = __float2half(w);
    } else {
        const int o = r >> 8, k = r & 255;
        const int half = m - 15;
        Wf[((size_t)m << 16) + r] = __float2half(sq_w[o*512 + half*256 + k]);
    }
}
__global__ void xtoh_kernel(const float4* __restrict__ X, __half* __restrict__ Xf)
{
    const size_t i = (size_t)blockIdx.x * 256 + threadIdx.x;
    float4 v = X[i];
    __half2 a = __floats2half2_rn(v.x, v.y), b = __floats2half2_rn(v.z, v.w);
    uint2 p;
    p.x = *(uint32_t*)&a; p.y = *(uint32_t*)&b;
    *(uint2*)(Xf + i * 4) = p;
}

// ----------------------------------------------------------------------------
// Window attention: all 3 branches in one launch. grid (1024, 12), block 128.
// ----------------------------------------------------------------------------
template<int WS>
__device__ __forceinline__ void winattn_body(
    const uint4* __restrict__ Q8, const uint4* __restrict__ K8,
    const uint4* __restrict__ V8, uint4* __restrict__ C8,
    float4 (*sK)[9], float4 (*sV)[9], int head, int bx, int tt)
{
    constexpr int WIN = WS*WS;
    constexpr int G   = 64 / WIN;
    constexpr int NW  = HIMG / WS;
    const int g  = tt / WIN;
    const int qi = tt % WIN;
    const int widx = bx * G + g;
    const int b   = widx / (NW*NW);
    const int rem = widx % (NW*NW);
    const int p1 = rem / NW, p2 = rem % NW;
    const int r  = p1*WS + qi/WS;
    const int cc = p2*WS + qi%WS;
    const int token = (b*HIMG + r)*WIMG + cc;
    const size_t base8 = (size_t)token*(CH/8) + head*(HS/8);

    float4 q[8];
    #pragma unroll
    for (int d = 0; d < 4; d++) {
        u4_to_f4x2(Q8[base8 + d], q[2*d], q[2*d + 1]);
        float4 ka, kb, va, vb;
        u4_to_f4x2(K8[base8 + d], ka, kb);
        u4_to_f4x2(V8[base8 + d], va, vb);
        sK[tt][2*d] = ka; sK[tt][2*d + 1] = kb;
        sV[tt][2*d] = va; sV[tt][2*d + 1] = vb;
    }
    __syncthreads();

    const float scale = 0.17677669529663687f;
    float sc[WIN];
    float mx = -1e30f;
    #pragma unroll
    for (int v = 0; v < WIN; v++) {
        float dot = 0.f;
        #pragma unroll
        for (int d = 0; d < 8; d++) {
            float4 k4 = sK[g*WIN + v][d];
            dot += q[d].x*k4.x + q[d].y*k4.y + q[d].z*k4.z + q[d].w*k4.w;
        }
        dot *= scale;
        sc[v] = dot;
        mx = fmaxf(mx, dot);
    }
    float sum = 0.f;
    #pragma unroll
    for (int v = 0; v < WIN; v++) { sc[v] = expf(sc[v] - mx); sum += sc[v]; }
    const float inv = 1.f / sum;
    #pragma unroll
    for (int v = 0; v < WIN; v++) sc[v] *= inv;

    #pragma unroll
    for (int dd = 0; dd < 4; dd++) {
        float4 a0 = make_float4(0.f, 0.f, 0.f, 0.f);
        float4 a1 = make_float4(0.f, 0.f, 0.f, 0.f);
        #pragma unroll
        for (int v = 0; v < WIN; v++) {
            float4 v0 = sV[g*WIN + v][2*dd];
            float4 v1 = sV[g*WIN + v][2*dd + 1];
            a0.x += sc[v]*v0.x; a0.y += sc[v]*v0.y;
            a0.z += sc[v]*v0.z; a0.w += sc[v]*v0.w;
            a1.x += sc[v]*v1.x; a1.y += sc[v]*v1.y;
            a1.z += sc[v]*v1.z; a1.w += sc[v]*v1.w;
        }
        C8[base8 + dd] = f4x2_to_u4(a0, a1);
    }
}

__global__ __launch_bounds__(128)
void winattn_all(const __half* __restrict__ QKVbase, __half* __restrict__ CTXbase)
{
    __shared__ float4 sK[2][64][9];
    __shared__ float4 sV[2][64][9];
    const int t = threadIdx.x, slot = t >> 6, tt = t & 63;
    const int br = blockIdx.y >> 2, hp = blockIdx.y & 3;
    const int head = hp*2 + slot;
    const uint4* Q8 = (const uint4*)(QKVbase + (size_t)(br*3 + 0)*NTOK*CH);
    const uint4* K8 = (const uint4*)(QKVbase + (size_t)(br*3 + 1)*NTOK*CH);
    const uint4* V8 = (const uint4*)(QKVbase + (size_t)(br*3 + 2)*NTOK*CH);
    uint4* C8 = (uint4*)(CTXbase + (size_t)br*NTOK*CH);
    if (br == 0)      winattn_body<2>(Q8, K8, V8, C8, sK[slot], sV[slot], head, blockIdx.x, tt);
    else if (br == 1) winattn_body<4>(Q8, K8, V8, C8, sK[slot], sV[slot], head, blockIdx.x, tt);
    else              winattn_body<8>(Q8, K8, V8, C8, sK[slot], sV[slot], head, blockIdx.x, tt);
}

// ----------------------------------------------------------------------------
// Edge selector
// ----------------------------------------------------------------------------
__global__ void conv9_kernel(const __half* __restrict__ x,
                             const float* __restrict__ ew,
                             float* __restrict__ t9)
{
    __shared__ float sw[CH*9];
    const int tid = threadIdx.x;
    for (int i = tid; i < CH*9; i += 256) sw[i] = ew[i];
    __syncthreads();

    const int warp = tid >> 5, lane = tid & 31;
    #pragma unroll
    for (int pp = 0; pp < 4; pp++) {
        const int pix = blockIdx.x * 32 + warp * 4 + pp;
        const uint4 v = ((const uint4*)(x + (size_t)pix*CH))[lane];
        float4 fa, fb;
        u4_to_f4x2(v, fa, fb);
        float xa[8] = {fa.x, fa.y, fa.z, fa.w, fb.x, fb.y, fb.z, fb.w};

        float acc[9] = {};
        #pragma unroll
        for (int i = 0; i < 8; i++) {
            const int c = lane*8 + i;
            #pragma unroll
            for (int k = 0; k < 9; k++) acc[k] += xa[i] * sw[c*9 + k];
        }
        #pragma unroll
        for (int k = 0; k < 9; k++)
            #pragma unroll
            for (int o = 16; o; o >>= 1)
                acc[k] += __shfl_xor_sync(0xffffffffu, acc[k], o);
        if (lane < 9) t9[(size_t)pix*9 + lane] = acc[lane];
    }
}

__global__ void edge_stencil_kernel(const float* __restrict__ t9,
                                    float* __restrict__ edge)
{
    const int pix = blockIdx.x * 256 + threadIdx.x;
    const int b = pix >> 12, y = (pix >> 6) & 63, xx = pix & 63;
    float s = 0.f;
    #pragma unroll
    for (int ky = 0; ky < 3; ky++) {
        const int yy = y + ky - 1;
        if (yy < 0 || yy > 63) continue;
        #pragma unroll
        for (int kx = 0; kx < 3; kx++) {
            const int xw = xx + kx - 1;
            if (xw < 0 || xw > 63) continue;
            s += t9[(size_t)((b*64 + yy)*64 + xw)*9 + ky*3 + kx];
        }
    }
    edge[pix] = fabsf(s);
}

__global__ void wts_kernel(const float* __restrict__ edge,
                           const float* __restrict__ w1, const float* __restrict__ b1,
                           const float* __restrict__ w2, const float* __restrict__ b2,
                           float* __restrict__ wts)
{
    int pix = blockIdx.x * blockDim.x + threadIdx.x;
    if (pix >= NTOK) return;
    int b = pix >> 12, y = (pix >> 6) & 63, xx = pix & 63;
    float s = 0.f;
    for (int dy = -1; dy <= 1; dy++) {
        int yy = y + dy; if (yy < 0 || yy > 63) continue;
        for (int dx = -1; dx <= 1; dx++) {
            int xw = xx + dx; if (xw < 0 || xw > 63) continue;
            s += edge[(b*64 + yy)*64 + xw];
        }
    }
    float e = s * (1.f/9.f);
    float lg[3] = {b2[0], b2[1], b2[2]};
    #pragma unroll
    for (int j = 0; j < 16; j++) {
        float h = fmaxf(e * w1[j] + b1[j], 0.f);
        lg[0] += h * w2[j*3 + 0];
        lg[1] += h * w2[j*3 + 1];
        lg[2] += h * w2[j*3 + 2];
    }
    float mx = fmaxf(lg[0], fmaxf(lg[1], lg[2]));
    float e0 = expf(lg[0]-mx), e1 = expf(lg[1]-mx), e2 = expf(lg[2]-mx);
    float inv = 1.f / (e0 + e1 + e2);
    wts[pix*3+0] = e0*inv;
    wts[pix*3+1] = e1*inv;
    wts[pix*3+2] = e2*inv;
}

// ----------------------------------------------------------------------------
// DlightConv
// ----------------------------------------------------------------------------
__global__ void dlight_kernel(const __half* __restrict__ S1,
                              const float* __restrict__ dlw,
                              const float* __restrict__ dlb,
                              __half* __restrict__ xdlf)
{
    __shared__ float part[8][16];
    __shared__ float probs[16];
    const int bx = blockIdx.x;
    const int b = bx >> 8, p1 = (bx >> 4) & 15, p2 = bx & 15;
    const int c = threadIdx.x;

    float vals[16];
    float mean = 0.f;
    #pragma unroll
    for (int wi = 0; wi < 16; wi++) {
        int r = p1*4 + (wi >> 2), cc = p2*4 + (wi & 3);
        vals[wi] = __half2float(S1[((size_t)((b*64 + r)*64 + cc))*CH + c]);
        mean += vals[wi];
    }
    mean *= (1.f/16.f);

    float contrib[16];
    #pragma unroll
    for (int j = 0; j < 16; j++) contrib[j] = mean * dlw[c*16 + j];
    #pragma unroll
    for (int j = 0; j < 16; j++)
        #pragma unroll
        for (int o = 16; o; o >>= 1)
            contrib[j] += __shfl_xor_sync(0xffffffffu, contrib[j], o);
    if ((c & 31) == 0) {
        #pragma unroll
        for (int j = 0; j < 16; j++) part[c >> 5][j] = contrib[j];
    }
    __syncthreads();
    if (c == 0) {
        float lg[16], mx = -1e30f;
        #pragma unroll
        for (int j = 0; j < 16; j++) {
            float v = dlb[j];
            #pragma unroll
            for (int w = 0; w < 8; w++) v += part[w][j];
            lg[j] = v;
            mx = fmaxf(mx, v);
        }
        float sum = 0.f;
        #pragma unroll
        for (int j = 0; j < 16; j++) { lg[j] = expf(lg[j] - mx); sum += lg[j]; }
        float inv = 1.f / sum;
        #pragma unroll
        for (int j = 0; j < 16; j++) probs[j] = lg[j] * inv;
    }
    __syncthreads();
    float acc = 0.f;
    #pragma unroll
    for (int wi = 0; wi < 16; wi++) acc += vals[wi] * probs[wi];
    xdlf[(size_t)bx*CH + c] = __float2half(acc);
}

// ----------------------------------------------------------------------------
// Fused axial attention (both axes, atomicAdd into pre-zeroed xg32)
// ----------------------------------------------------------------------------
__global__ void axial_fused(const float* __restrict__ Q,
                            const float* __restrict__ K,
                            const float* __restrict__ V,
                            const float* __restrict__ gsp,
                            const float* __restrict__ gbp,
                            float* __restrict__ out32)
{
    __shared__ float sQ[16][CH];
    __shared__ float sK[16][CH];
    __shared__ float sc[16][17];
    const int axis = blockIdx.y;
    const int blk = blockIdx.x;
    const int b = blk >> 4, f = blk & 15;
    const int t = threadIdx.x;

    for (int idx = t; idx < 16*CH; idx += 256) {
        int i = idx >> 8, c = idx & 255;
        size_t tok = (axis == 0) ? (size_t)((b*16 + f)*16 + i)
                                 : (size_t)((b*16 + i)*16 + f);
        sQ[i][c] = Q[tok*CH + c];
        sK[i][c] = K[tok*CH + c];
    }
    __syncthreads();

    {
        int w = t >> 4, v = t & 15;
        float dot = 0.f;
        #pragma unroll 8
        for (int c = 0; c < CH; c++) dot += sQ[w][c] * sK[v][c];
        float gs = gsp[0], gb0 = gbp[0];
        float d2 = (float)((v - w) * (v - w));
        sc[w][v] = dot - (gs * d2 + gb0);
    }
    __syncthreads();
    if (t < 16) {
        float mx = -1e30f;
        #pragma unroll
        for (int v = 0; v < 16; v++) mx = fmaxf(mx, sc[t][v]);
        float sum = 0.f;
        #pragma unroll
        for (int v = 0; v < 16; v++) { float e = expf(sc[t][v] - mx); sc[t][v] = e; sum += e; }
        float inv = 1.f / sum;
        #pragma unroll
        for (int v = 0; v < 16; v++) sc[t][v] *= inv;
    }
    __syncthreads();

    const int d = t;
    float acc[16] = {};
    #pragma unroll
    for (int v = 0; v < 16; v++) {
        size_t tokv = (axis == 0) ? (size_t)((b*16 + f)*16 + v)
                                  : (size_t)((b*16 + v)*16 + f);
        float vv = V[tokv*CH + d];
        #pragma unroll
        for (int w = 0; w < 16; w++) acc[w] += sc[w][v] * vv;
    }
    #pragma unroll
    for (int w = 0; w < 16; w++) {
        size_t tokw = (axis == 0) ? (size_t)((b*16 + f)*16 + w)
                                  : (size_t)((b*16 + w)*16 + f);
        atomicAdd(&out32[tokw*CH + d], acc[w]);
    }
}

__global__ void xg32toh(const float4* __restrict__ X, __half* __restrict__ Xh)
{
    const size_t i = (size_t)blockIdx.x * 256 + threadIdx.x;
    float4 v = X[i];
    __half2 a = __floats2half2_rn(v.x, v.y), b = __floats2half2_rn(v.z, v.w);
    uint2 p;
    p.x = *(uint32_t*)&a; p.y = *(uint32_t*)&b;
    *(uint2*)(Xh + i * 4) = p;
}

// ----------------------------------------------------------------------------
// Host launch — round-12 legal DAG + gemm_upz fusion
// ----------------------------------------------------------------------------
extern "C" void kernel_launch(void* const* d_in, const int* in_sizes, int n_in,
                              void* d_out, int out_size)
{
    const float* x      = (const float*)d_in[0];
    const float* attn_w = (const float*)d_in[1];
    const float* attn_b = (const float*)d_in[2];
    const float* edge_w = (const float*)d_in[3];
    const float* mlp_w1 = (const float*)d_in[4];
    const float* mlp_b1 = (const float*)d_in[5];
    const float* mlp_w2 = (const float*)d_in[6];
    const float* mlp_b2 = (const float*)d_in[7];
    const float* dl_w   = (const float*)d_in[8];
    const float* dl_b   = (const float*)d_in[9];
    const float* ax_w   = (const float*)d_in[10];
    const float* ax_b   = (const float*)d_in[11];
    const float* g_sh   = (const float*)d_in[12];
    const float* g_bi   = (const float*)d_in[13];
    const float* sq_w   = (const float*)d_in[14];
    const float* sq_b   = (const float*)d_in[15];
    float* out = (float*)d_out;

    __half *QKVh, *CTXh, *Sh, *Xf, *Wf, *XDLf, *XGH;
    float *T9b, *EDGEb, *WTSb, *AQb, *AKb, *AVb, *XG32, *Yb, *ZB0;
    cudaGetSymbolAddress((void**)&QKVh, g_QKV);
    cudaGetSymbolAddress((void**)&CTXh, g_CTX);
    cudaGetSymbolAddress((void**)&Sh,   g_S);
    cudaGetSymbolAddress((void**)&Xf,   g_xf);
    cudaGetSymbolAddress((void**)&Wf,   g_Wf);
    cudaGetSymbolAddress((void**)&XDLf, g_xdlf);
    cudaGetSymbolAddress((void**)&XGH,  g_xgh);
    cudaGetSymbolAddress((void**)&T9b,  g_t9);
    cudaGetSymbolAddress((void**)&EDGEb,g_edge);
    cudaGetSymbolAddress((void**)&WTSb, g_wts);
    cudaGetSymbolAddress((void**)&AQb,  g_aQ);
    cudaGetSymbolAddress((void**)&AKb,  g_aK);
    cudaGetSymbolAddress((void**)&AVb,  g_aV);
    cudaGetSymbolAddress((void**)&XG32, g_xg32);
    cudaGetSymbolAddress((void**)&Yb,   g_y);
    cudaGetSymbolAddress((void**)&ZB0,  g_zerob);

    cudaStream_t s_aux;
    cudaStreamCreateWithFlags(&s_aux, cudaStreamNonBlocking);
    cudaEvent_t evX, evE, evS1, evY;
    cudaEventCreateWithFlags(&evX,  cudaEventDisableTiming);
    cudaEventCreateWithFlags(&evE,  cudaEventDisableTiming);
    cudaEventCreateWithFlags(&evS1, cudaEventDisableTiming);
    cudaEventCreateWithFlags(&evY,  cudaEventDisableTiming);

    // ---- main: conversions (capture origin stays on main) ----
    convw_all<<<17*65536/256, 256>>>(attn_w, ax_w, sq_w, Wf);
    xtoh_kernel<<<NTOK*CH/4/256, 256>>>((const float4*)x, Xf);
    cudaEventRecord(evX, 0);

    // ---- aux: edge-selector path (forked AFTER main event; capture-legal) ----
    cudaStreamWaitEvent(s_aux, evX, 0);
    conv9_kernel<<<NTOK/32, 256, 0, s_aux>>>(Xf, edge_w, T9b);
    edge_stencil_kernel<<<NTOK/256, 256, 0, s_aux>>>(T9b, EDGEb);
    wts_kernel<<<NTOK/256, 256, 0, s_aux>>>(EDGEb, mlp_w1, mlp_b1, mlp_w2, mlp_b2, WTSb);
    cudaEventRecord(evE, s_aux);

    // ---- main: fused QKV projections ----
    {
        TilesT<__half, 9> Tq;
        for (int br = 0; br < 3; br++)
            for (int j = 0; j < 3; j++) {
                const int s = br*3 + j;
                Tq.t[s].a = Xf;
                Tq.t[s].b = Wf + (size_t)(br*4 + j)*65536;
                Tq.t[s].bias = attn_b + (br*4 + j)*CH;
                Tq.t[s].out  = QKVh + (size_t)s*NTOK*CH;
            }
        gemm_h<<<dim3(18, NTOK/128), 256, GEMM_SMEM>>>(Tq, 256);
    }

    // ---- main: window attention (all branches, one launch) ----
    winattn_all<<<dim3(1024, 12), 128>>>(QKVh, CTXh);

    // ---- main: out-proj S1 first ----
    {
        TilesT<__half, 1> To;
        To.t[0].a = CTXh + (size_t)1*NTOK*CH;
        To.t[0].b = Wf + (size_t)(1*4 + 3)*65536;
        To.t[0].bias = attn_b + (1*4 + 3)*CH;
        To.t[0].out  = Sh + (size_t)1*NTOK*CH;
        gemm_h<<<dim3(2, NTOK/128), 256, GEMM_SMEM>>>(To, 256);
    }
    cudaEventRecord(evS1, 0);

    // ---- aux: pooled/axial chain (hidden under S0/S2 out-proj) ----
    cudaStreamWaitEvent(s_aux, evS1, 0);
    dlight_kernel<<<NDTOK, 256, 0, s_aux>>>(Sh + (size_t)1*NTOK*CH, dl_w, dl_b, XDLf);
    {
        TilesT<float, 3> Ta;
        float* aqkv[3] = {AQb, AKb, AVb};
        for (int m = 0; m < 3; m++) {
            Ta.t[m].a = XDLf;
            Ta.t[m].b = Wf + WF_AX + (size_t)m*65536;
            Ta.t[m].bias = ax_b + m*CH;
            Ta.t[m].out  = aqkv[m];
        }
        gemm_h<<<dim3(6, NDTOK/128), 256, GEMM_SMEM, s_aux>>>(Ta, 256);
    }
    cudaMemsetAsync(XG32, 0, (size_t)NDTOK*CH*sizeof(float), s_aux);
    axial_fused<<<dim3(BSZ*PP, 2), 256, 0, s_aux>>>(AQb, AKb, AVb, g_sh, g_bi, XG32);
    xg32toh<<<NDTOK*CH/4/256, 256, 0, s_aux>>>((const float4*)XG32, XGH);
    {
        TilesT<float, 1> Ty;
        Ty.t[0].a = XGH;
        Ty.t[0].b = Wf + WF_SQ1;
        Ty.t[0].bias = ZB0;
        Ty.t[0].out  = Yb;
        gemm_h<<<dim3(2, NDTOK/128), 256, GEMM_SMEM, s_aux>>>(Ty, 256);
    }
    cudaEventRecord(evY, s_aux);

    // ---- main: out-proj S0 + S2 (concurrent with aux pooled chain) ----
    {
        TilesT<__half, 2> To;
        const int brs[2] = {0, 2};
        for (int i = 0; i < 2; i++) {
            const int br = brs[i];
            To.t[i].a = CTXh + (size_t)br*NTOK*CH;
            To.t[i].b = Wf + (size_t)(br*4 + 3)*65536;
            To.t[i].bias = attn_b + (br*4 + 3)*CH;
            To.t[i].out  = Sh + (size_t)br*NTOK*CH;
        }
        gemm_h<<<dim3(4, NTOK/128), 256, GEMM_SMEM>>>(To, 256);
    }

    // ---- main: final (fused blend + up(y) epilogue) ----
    cudaStreamWaitEvent(0, evE, 0);
    cudaStreamWaitEvent(0, evY, 0);
    gemm_upz<<<dim3(2, NTOK/128), 256, GEMM_SMEM>>>(
        Sh + (size_t)0*NTOK*CH,
        Sh + (size_t)1*NTOK*CH,
        Sh + (size_t)2*NTOK*CH,
        WTSb, Wf + WF_SQ2, sq_b, Yb, out);

    cudaEventDestroy(evX);
    cudaEventDestroy(evE);
    cudaEventDestroy(evS1);
    cudaEventDestroy(evY);
    cudaStreamDestroy(s_aux);
}

// round 15
// speedup vs baseline: 1.0057x; 1.0057x over previous
#include <cuda_runtime.h>
#include <cuda_fp16.h>
#include <math.h>
#include <stdint.h>

// ----------------------------------------------------------------------------
// Problem constants
// ----------------------------------------------------------------------------
#define BSZ   16
#define HIMG  64
#define WIMG  64
#define CH    256
#define NTOK  (BSZ*HIMG*WIMG)       // 65536
#define NHEAD 8
#define HS    32
#define PP    16
#define NDTOK (BSZ*PP*PP)           // 4096

// fp16 weight slots ([N][K]): 12 attn + 3 axial + sq1 + sq2
#define WF_ATTN 0
#define WF_AX   (12*65536)
#define WF_SQ1  (15*65536)
#define WF_SQ2  (16*65536)
#define WFTOT   (17*65536)

// ----------------------------------------------------------------------------
// Scratch
// ----------------------------------------------------------------------------
__device__ __half g_QKV[9][NTOK*CH];
__device__ __half g_CTX[3][NTOK*CH];
__device__ __half g_S[3][NTOK*CH];
__device__ __half g_xf[NTOK*CH];
__device__ __half g_Zb[NTOK*CH];
__device__ __half g_Wf[WFTOT];
__device__ __half g_xdlf[NDTOK*CH];
__device__ __half g_xgh[NDTOK*CH];
__device__ float  g_y[NDTOK*CH];
__device__ float  g_zerob[CH];
__device__ float  g_t9[NTOK*9];
__device__ float  g_edge[NTOK];
__device__ float  g_wts[NTOK*3];
__device__ float  g_aQ[NDTOK*CH];
__device__ float  g_aK[NDTOK*CH];
__device__ float  g_aV[NDTOK*CH];
__device__ float  g_xg32[NDTOK*CH];

// ----------------------------------------------------------------------------
// PTX helpers
// ----------------------------------------------------------------------------
__device__ __forceinline__ uint32_t smem_u32(const void* p) {
    uint32_t a;
    asm("{ .reg .u64 t; cvta.to.shared.u64 t, %1; cvt.u32.u64 %0, t; }"
        : "=r"(a) : "l"(p));
    return a;
}
__device__ __forceinline__ void ldsm4(uint32_t* r, uint32_t addr) {
    asm volatile("ldmatrix.sync.aligned.m8n8.x4.shared.b16 {%0,%1,%2,%3}, [%4];"
                 : "=r"(r[0]), "=r"(r[1]), "=r"(r[2]), "=r"(r[3]) : "r"(addr));
}
__device__ __forceinline__ void mma_f16(float* d, const uint32_t* a,
                                        uint32_t b0, uint32_t b1) {
    asm volatile("mma.sync.aligned.m16n8k16.row.col.f32.f16.f16.f32 "
                 "{%0,%1,%2,%3}, {%4,%5,%6,%7}, {%8,%9}, {%0,%1,%2,%3};"
                 : "+f"(d[0]), "+f"(d[1]), "+f"(d[2]), "+f"(d[3])
                 : "r"(a[0]), "r"(a[1]), "r"(a[2]), "r"(a[3]), "r"(b0), "r"(b1));
}
#define CP16(dst, src) \
    asm volatile("cp.async.cg.shared.global [%0], [%1], 16;" :: "r"(dst), "l"(src))
#define CP_COMMIT() asm volatile("cp.async.commit_group;" ::: "memory")
#define CP_WAIT0()  asm volatile("cp.async.wait_group 0;" ::: "memory")

__device__ __forceinline__ void u4_to_f4x2(uint4 r, float4& a, float4& b) {
    __half2 h0 = *(__half2*)&r.x, h1 = *(__half2*)&r.y;
    __half2 h2 = *(__half2*)&r.z, h3 = *(__half2*)&r.w;
    float2 f0 = __half22float2(h0), f1 = __half22float2(h1);
    float2 f2 = __half22float2(h2), f3 = __half22float2(h3);
    a = make_float4(f0.x, f0.y, f1.x, f1.y);
    b = make_float4(f2.x, f2.y, f3.x, f3.y);
}
__device__ __forceinline__ uint4 f4x2_to_u4(float4 a, float4 b) {
    __half2 h0 = __floats2half2_rn(a.x, a.y), h1 = __floats2half2_rn(a.z, a.w);
    __half2 h2 = __floats2half2_rn(b.x, b.y), h3 = __floats2half2_rn(b.z, b.w);
    uint4 r;
    r.x = *(uint32_t*)&h0; r.y = *(uint32_t*)&h1;
    r.z = *(uint32_t*)&h2; r.w = *(uint32_t*)&h3;
    return r;
}
__device__ __forceinline__ void store2(float* p, float a, float b) {
    *(float2*)p = make_float2(a, b);
}
__device__ __forceinline__ void store2(__half* p, float a, float b) {
    *(__half2*)p = __floats2half2_rn(a, b);
}

// ----------------------------------------------------------------------------
// fp16 GEMM (round-7 proven config)
// ----------------------------------------------------------------------------
template<typename OT> struct TileT {
    const __half *a, *b;
    const float* bias;
    OT* out;
};
template<typename OT, int NM> struct TilesT { TileT<OT> t[NM]; };

#define SMH_A   0
#define SMH_B   10240
#define SMH_BUF 20480
#define GEMM_SMEM (2*SMH_BUF)

template<typename OT>
__device__ __forceinline__ void load_chunkh(
    uint32_t sbase, const TileT<OT>& e, int K, int row0, int col0, int k0, int t)
{
    const int lrow = t >> 1;
    const int lseg = (t & 1) * 16;
    const uint32_t doff = (uint32_t)(lrow * 80 + lseg * 2);
    const __half* s = e.a + (size_t)(row0 + lrow) * K + k0 + lseg;
    CP16(sbase + SMH_A + doff,      s);
    CP16(sbase + SMH_A + doff + 16, s + 8);
    s = e.b + (size_t)(col0 + lrow) * K + k0 + lseg;
    CP16(sbase + SMH_B + doff,      s);
    CP16(sbase + SMH_B + doff + 16, s + 8);
}

template<typename OT, int NM>
__global__ __launch_bounds__(256)
void gemm_h(TilesT<OT, NM> T, int K)
{
    extern __shared__ char sm[];
    const uint32_t sb0 = smem_u32(sm);

    const int t = threadIdx.x;
    const int wid = t >> 5, lane = t & 31;
    const TileT<OT> e = T.t[blockIdx.x >> 1];
    const int col0 = (blockIdx.x & 1) * 128;
    const int row0 = blockIdx.y * 128;
    const int mw = wid & 3;
    const int nw = wid >> 2;
    const int NC = K >> 5;

    float acc[2][8][4];
    #pragma unroll
    for (int i = 0; i < 2; i++)
        #pragma unroll
        for (int j = 0; j < 8; j++)
            #pragma unroll
            for (int q = 0; q < 4; q++) acc[i][j][q] = 0.f;

    load_chunkh(sb0, e, K, row0, col0, 0, t);
    CP_COMMIT();

    const uint32_t a_off[2] = {
        (uint32_t)((mw*32 + 0*16 + (lane & 15)) * 80),
        (uint32_t)((mw*32 + 1*16 + (lane & 15)) * 80)
    };
    const uint32_t a_col = (uint32_t)(((lane >> 4) << 3) * 2);
    uint32_t b_off[4];
    #pragma unroll
    for (int j = 0; j < 4; j++)
        b_off[j] = (uint32_t)((nw*64 + j*16 + (lane & 7) + ((lane >> 4) << 3)) * 80);
    const uint32_t b_col = (uint32_t)((((lane >> 3) & 1) << 3) * 2);

    for (int c = 0; c < NC; c++) {
        CP_WAIT0();
        __syncthreads();
        if (c + 1 < NC) {
            load_chunkh(sb0 + (uint32_t)((c + 1) & 1) * SMH_BUF, e, K, row0, col0,
                        (c + 1) << 5, t);
            CP_COMMIT();
        }
        const uint32_t bb = sb0 + (uint32_t)(c & 1) * SMH_BUF;

        #pragma unroll
        for (int ks = 0; ks < 2; ks++) {
            const uint32_t kc = (uint32_t)(ks * 32);
            uint32_t af[2][4], bf[4][4];
            #pragma unroll
            for (int mt = 0; mt < 2; mt++)
                ldsm4(af[mt], bb + SMH_A + a_off[mt] + kc + a_col);
            #pragma unroll
            for (int j = 0; j < 4; j++)
                ldsm4(bf[j], bb + SMH_B + b_off[j] + kc + b_col);
            #pragma unroll
            for (int mt = 0; mt < 2; mt++)
                #pragma unroll
                for (int j = 0; j < 4; j++) {
                    mma_f16(acc[mt][2*j],     af[mt], bf[j][0], bf[j][1]);
                    mma_f16(acc[mt][2*j + 1], af[mt], bf[j][2], bf[j][3]);
                }
        }
        __syncthreads();
    }

    #pragma unroll
    for (int mt = 0; mt < 2; mt++) {
        const int r_ = row0 + mw*32 + mt*16 + (lane >> 2);
        #pragma unroll
        for (int j = 0; j < 8; j++) {
            const int c_ = col0 + nw*64 + j*8 + (lane & 3)*2;
            const float b0 = e.bias[c_], b1 = e.bias[c_ + 1];
            store2(&e.out[(size_t)r_ * 256 + c_],       acc[mt][j][0] + b0, acc[mt][j][1] + b1);
            store2(&e.out[(size_t)(r_ + 8) * 256 + c_], acc[mt][j][2] + b0, acc[mt][j][3] + b1);
        }
    }
}

// ----------------------------------------------------------------------------
// Final GEMM: out = Zb @ W2^T + sq_b + bilerp(y)
// ----------------------------------------------------------------------------
__global__ __launch_bounds__(256)
void gemm_up(const __half* __restrict__ A, const __half* __restrict__ B,
             const float* __restrict__ bias, const float* __restrict__ y,
             float* __restrict__ Cm)
{
    extern __shared__ char sm[];
    const uint32_t sb0 = smem_u32(sm);

    const int t = threadIdx.x;
    const int wid = t >> 5, lane = t & 31;
    const int col0 = (blockIdx.x & 1) * 128;
    const int row0 = blockIdx.y * 128;
    const int mw = wid & 3;
    const int nw = wid >> 2;
    const int NC = 8;
    const int K = 256;

    TileT<float> e;
    e.a = A; e.b = B; e.bias = bias; e.out = Cm;

    float acc[2][8][4];
    #pragma unroll
    for (int i = 0; i < 2; i++)
        #pragma unroll
        for (int j = 0; j < 8; j++)
            #pragma unroll
            for (int q = 0; q < 4; q++) acc[i][j][q] = 0.f;

    load_chunkh(sb0, e, K, row0, col0, 0, t);
    CP_COMMIT();

    const uint32_t a_off[2] = {
        (uint32_t)((mw*32 + 0*16 + (lane & 15)) * 80),
        (uint32_t)((mw*32 + 1*16 + (lane & 15)) * 80)
    };
    const uint32_t a_col = (uint32_t)(((lane >> 4) << 3) * 2);
    uint32_t b_off[4];
    #pragma unroll
    for (int j = 0; j < 4; j++)
        b_off[j] = (uint32_t)((nw*64 + j*16 + (lane & 7) + ((lane >> 4) << 3)) * 80);
    const uint32_t b_col = (uint32_t)((((lane >> 3) & 1) << 3) * 2);

    for (int c = 0; c < NC; c++) {
        CP_WAIT0();
        __syncthreads();
        if (c + 1 < NC) {
            load_chunkh(sb0 + (uint32_t)((c + 1) & 1) * SMH_BUF, e, K, row0, col0,
                        (c + 1) << 5, t);
            CP_COMMIT();
        }
        const uint32_t bb = sb0 + (uint32_t)(c & 1) * SMH_BUF;

        #pragma unroll
        for (int ks = 0; ks < 2; ks++) {
            const uint32_t kc = (uint32_t)(ks * 32);
            uint32_t af[2][4], bf[4][4];
            #pragma unroll
            for (int mt = 0; mt < 2; mt++)
                ldsm4(af[mt], bb + SMH_A + a_off[mt] + kc + a_col);
            #pragma unroll
            for (int j = 0; j < 4; j++)
                ldsm4(bf[j], bb + SMH_B + b_off[j] + kc + b_col);
            #pragma unroll
            for (int mt = 0; mt < 2; mt++)
                #pragma unroll
                for (int j = 0; j < 4; j++) {
                    mma_f16(acc[mt][2*j],     af[mt], bf[j][0], bf[j][1]);
                    mma_f16(acc[mt][2*j + 1], af[mt], bf[j][2], bf[j][3]);
                }
        }
        __syncthreads();
    }

    const float scl = 15.f / 63.f;
    #pragma unroll
    for (int mt = 0; mt < 2; mt++) {
        #pragma unroll
        for (int hh = 0; hh < 2; hh++) {
            const int pix = row0 + mw*32 + mt*16 + (lane >> 2) + hh*8;
            const int bimg = pix >> 12, yy = (pix >> 6) & 63, xx = pix & 63;
            float pr = yy * scl;
            int r0 = (int)floorf(pr);
            float tr = pr - (float)r0;
            int r1 = min(r0 + 1, 15);
            float pc = xx * scl;
            int c0i = (int)floorf(pc);
            float tc = pc - (float)c0i;
            int c1i = min(c0i + 1, 15);
            const float* yb = y + (size_t)bimg * 256 * CH;
            const float* y00 = yb + (r0*16 + c0i)*CH;
            const float* y01 = yb + (r0*16 + c1i)*CH;
            const float* y10 = yb + (r1*16 + c0i)*CH;
            const float* y11 = yb + (r1*16 + c1i)*CH;
            const float w00 = (1.f-tr)*(1.f-tc), w01 = (1.f-tr)*tc;
            const float w10 = tr*(1.f-tc),       w11 = tr*tc;
            #pragma unroll
            for (int j = 0; j < 8; j++) {
                const int c_ = col0 + nw*64 + j*8 + (lane & 3)*2;
                float2 v00 = *(const float2*)&y00[c_];
                float2 v01 = *(const float2*)&y01[c_];
                float2 v10 = *(const float2*)&y10[c_];
                float2 v11 = *(const float2*)&y11[c_];
                float up0 = w00*v00.x + w01*v01.x + w10*v10.x + w11*v11.x;
                float up1 = w00*v00.y + w01*v01.y + w10*v10.y + w11*v11.y;
                const float a0 = acc[mt][j][hh*2 + 0], a1 = acc[mt][j][hh*2 + 1];
                store2(&Cm[(size_t)pix * 256 + c_],
                       a0 + bias[c_] + up0, a1 + bias[c_ + 1] + up1);
            }
        }
    }
}

// ----------------------------------------------------------------------------
// Fused conversions: blocks [0, XB) do x->fp16; blocks [XB, XB+WB) do weights
// ----------------------------------------------------------------------------
#define XB (NTOK*CH/4/256)      // 16384
#define WB (17*65536/256)       // 4352

__global__ void conv_fused(const float4* __restrict__ X, __half* __restrict__ Xf,
                           const float* __restrict__ attn_w,
                           const float* __restrict__ ax_w,
                           const float* __restrict__ sq_w,
                           __half* __restrict__ Wf)
{
    if (blockIdx.x < XB) {
        const size_t i = (size_t)blockIdx.x * 256 + threadIdx.x;
        float4 v = X[i];
        __half2 a = __floats2half2_rn(v.x, v.y), b = __floats2half2_rn(v.z, v.w);
        uint2 p;
        p.x = *(uint32_t*)&a; p.y = *(uint32_t*)&b;
        *(uint2*)(Xf + i * 4) = p;
    } else {
        const int idx = (blockIdx.x - XB) * 256 + threadIdx.x;
        const int m = idx >> 16, r = idx & 65535;
        if (m < 15) {
            const int k = r >> 8, n = r & 255;
            const float w = (m < 12) ? attn_w[idx] : ax_w[(m - 12)*65536 + r];
            Wf[((size_t)m << 16) + (n << 8) + k] = __float2half(w);
        } else {
            const int o = r >> 8, k = r & 255;
            const int half_ = m - 15;
            Wf[((size_t)m << 16) + r] = __float2half(sq_w[o*512 + half_*256 + k]);
        }
    }
}

// ----------------------------------------------------------------------------
// Window attention: all 3 branches in one launch. grid (1024, 12), block 128.
// ----------------------------------------------------------------------------
template<int WS>
__device__ __forceinline__ void winattn_body(
    const uint4* __restrict__ Q8, const uint4* __restrict__ K8,
    const uint4* __restrict__ V8, uint4* __restrict__ C8,
    float4 (*sK)[9], float4 (*sV)[9], int head, int bx, int tt)
{
    constexpr int WIN = WS*WS;
    constexpr int G   = 64 / WIN;
    constexpr int NW  = HIMG / WS;
    const int g  = tt / WIN;
    const int qi = tt % WIN;
    const int widx = bx * G + g;
    const int b   = widx / (NW*NW);
    const int rem = widx % (NW*NW);
    const int p1 = rem / NW, p2 = rem % NW;
    const int r  = p1*WS + qi/WS;
    const int cc = p2*WS + qi%WS;
    const int token = (b*HIMG + r)*WIMG + cc;
    const size_t base8 = (size_t)token*(CH/8) + head*(HS/8);

    float4 q[8];
    #pragma unroll
    for (int d = 0; d < 4; d++) {
        u4_to_f4x2(Q8[base8 + d], q[2*d], q[2*d + 1]);
        float4 ka, kb, va, vb;
        u4_to_f4x2(K8[base8 + d], ka, kb);
        u4_to_f4x2(V8[base8 + d], va, vb);
        sK[tt][2*d] = ka; sK[tt][2*d + 1] = kb;
        sV[tt][2*d] = va; sV[tt][2*d + 1] = vb;
    }
    __syncthreads();

    const float scale = 0.17677669529663687f;
    float sc[WIN];
    float mx = -1e30f;
    #pragma unroll
    for (int v = 0; v < WIN; v++) {
        float dot = 0.f;
        #pragma unroll
        for (int d = 0; d < 8; d++) {
            float4 k4 = sK[g*WIN + v][d];
            dot += q[d].x*k4.x + q[d].y*k4.y + q[d].z*k4.z + q[d].w*k4.w;
        }
        dot *= scale;
        sc[v] = dot;
        mx = fmaxf(mx, dot);
    }
    float sum = 0.f;
    #pragma unroll
    for (int v = 0; v < WIN; v++) { sc[v] = expf(sc[v] - mx); sum += sc[v]; }
    const float inv = 1.f / sum;
    #pragma unroll
    for (int v = 0; v < WIN; v++) sc[v] *= inv;

    #pragma unroll
    for (int dd = 0; dd < 4; dd++) {
        float4 a0 = make_float4(0.f, 0.f, 0.f, 0.f);
        float4 a1 = make_float4(0.f, 0.f, 0.f, 0.f);
        #pragma unroll
        for (int v = 0; v < WIN; v++) {
            float4 v0 = sV[g*WIN + v][2*dd];
            float4 v1 = sV[g*WIN + v][2*dd + 1];
            a0.x += sc[v]*v0.x; a0.y += sc[v]*v0.y;
            a0.z += sc[v]*v0.z; a0.w += sc[v]*v0.w;
            a1.x += sc[v]*v1.x; a1.y += sc[v]*v1.y;
            a1.z += sc[v]*v1.z; a1.w += sc[v]*v1.w;
        }
        C8[base8 + dd] = f4x2_to_u4(a0, a1);
    }
}

__global__ __launch_bounds__(128)
void winattn_all(const __half* __restrict__ QKVbase, __half* __restrict__ CTXbase)
{
    __shared__ float4 sK[2][64][9];
    __shared__ float4 sV[2][64][9];
    const int t = threadIdx.x, slot = t >> 6, tt = t & 63;
    const int br = blockIdx.y >> 2, hp = blockIdx.y & 3;
    const int head = hp*2 + slot;
    const uint4* Q8 = (const uint4*)(QKVbase + (size_t)(br*3 + 0)*NTOK*CH);
    const uint4* K8 = (const uint4*)(QKVbase + (size_t)(br*3 + 1)*NTOK*CH);
    const uint4* V8 = (const uint4*)(QKVbase + (size_t)(br*3 + 2)*NTOK*CH);
    uint4* C8 = (uint4*)(CTXbase + (size_t)br*NTOK*CH);
    if (br == 0)      winattn_body<2>(Q8, K8, V8, C8, sK[slot], sV[slot], head, blockIdx.x, tt);
    else if (br == 1) winattn_body<4>(Q8, K8, V8, C8, sK[slot], sV[slot], head, blockIdx.x, tt);
    else              winattn_body<8>(Q8, K8, V8, C8, sK[slot], sV[slot], head, blockIdx.x, tt);
}

// ----------------------------------------------------------------------------
// Edge selector
// ----------------------------------------------------------------------------
__global__ void conv9_kernel(const __half* __restrict__ x,
                             const float* __restrict__ ew,
                             float* __restrict__ t9)
{
    __shared__ float sw[CH*9];
    const int tid = threadIdx.x;
    for (int i = tid; i < CH*9; i += 256) sw[i] = ew[i];
    __syncthreads();

    const int warp = tid >> 5, lane = tid & 31;
    #pragma unroll
    for (int pp = 0; pp < 4; pp++) {
        const int pix = blockIdx.x * 32 + warp * 4 + pp;
        const uint4 v = ((const uint4*)(x + (size_t)pix*CH))[lane];
        float4 fa, fb;
        u4_to_f4x2(v, fa, fb);
        float xa[8] = {fa.x, fa.y, fa.z, fa.w, fb.x, fb.y, fb.z, fb.w};

        float acc[9] = {};
        #pragma unroll
        for (int i = 0; i < 8; i++) {
            const int c = lane*8 + i;
            #pragma unroll
            for (int k = 0; k < 9; k++) acc[k] += xa[i] * sw[c*9 + k];
        }
        #pragma unroll
        for (int k = 0; k < 9; k++)
            #pragma unroll
            for (int o = 16; o; o >>= 1)
                acc[k] += __shfl_xor_sync(0xffffffffu, acc[k], o);
        if (lane < 9) t9[(size_t)pix*9 + lane] = acc[lane];
    }
}

__global__ void edge_stencil_kernel(const float* __restrict__ t9,
                                    float* __restrict__ edge)
{
    const int pix = blockIdx.x * 256 + threadIdx.x;
    const int b = pix >> 12, y = (pix >> 6) & 63, xx = pix & 63;
    float s = 0.f;
    #pragma unroll
    for (int ky = 0; ky < 3; ky++) {
        const int yy = y + ky - 1;
        if (yy < 0 || yy > 63) continue;
        #pragma unroll
        for (int kx = 0; kx < 3; kx++) {
            const int xw = xx + kx - 1;
            if (xw < 0 || xw > 63) continue;
            s += t9[(size_t)((b*64 + yy)*64 + xw)*9 + ky*3 + kx];
        }
    }
    edge[pix] = fabsf(s);
}

__global__ void wts_kernel(const float* __restrict__ edge,
                           const float* __restrict__ w1, const float* __restrict__ b1,
                           const float* __restrict__ w2, const float* __restrict__ b2,
                           float* __restrict__ wts)
{
    int pix = blockIdx.x * blockDim.x + threadIdx.x;
    if (pix >= NTOK) return;
    int b = pix >> 12, y = (pix >> 6) & 63, xx = pix & 63;
    float s = 0.f;
    for (int dy = -1; dy <= 1; dy++) {
        int yy = y + dy; if (yy < 0 || yy > 63) continue;
        for (int dx = -1; dx <= 1; dx++) {
            int xw = xx + dx; if (xw < 0 || xw > 63) continue;
            s += edge[(b*64 + yy)*64 + xw];
        }
    }
    float e = s * (1.f/9.f);
    float lg[3] = {b2[0], b2[1], b2[2]};
    #pragma unroll
    for (int j = 0; j < 16; j++) {
        float h = fmaxf(e * w1[j] + b1[j], 0.f);
        lg[0] += h * w2[j*3 + 0];
        lg[1] += h * w2[j*3 + 1];
        lg[2] += h * w2[j*3 + 2];
    }
    float mx = fmaxf(lg[0], fmaxf(lg[1], lg[2]));
    float e0 = expf(lg[0]-mx), e1 = expf(lg[1]-mx), e2 = expf(lg[2]-mx);
    float inv = 1.f / (e0 + e1 + e2);
    wts[pix*3+0] = e0*inv;
    wts[pix*3+1] = e1*inv;
    wts[pix*3+2] = e2*inv;
}

// ----------------------------------------------------------------------------
// DlightConv
// ----------------------------------------------------------------------------
__global__ void dlight_kernel(const __half* __restrict__ S1,
                              const float* __restrict__ dlw,
                              const float* __restrict__ dlb,
                              __half* __restrict__ xdlf)
{
    __shared__ float part[8][16];
    __shared__ float probs[16];
    const int bx = blockIdx.x;
    const int b = bx >> 8, p1 = (bx >> 4) & 15, p2 = bx & 15;
    const int c = threadIdx.x;

    float vals[16];
    float mean = 0.f;
    #pragma unroll
    for (int wi = 0; wi < 16; wi++) {
        int r = p1*4 + (wi >> 2), cc = p2*4 + (wi & 3);
        vals[wi] = __half2float(S1[((size_t)((b*64 + r)*64 + cc))*CH + c]);
        mean += vals[wi];
    }
    mean *= (1.f/16.f);

    float contrib[16];
    #pragma unroll
    for (int j = 0; j < 16; j++) contrib[j] = mean * dlw[c*16 + j];
    #pragma unroll
    for (int j = 0; j < 16; j++)
        #pragma unroll
        for (int o = 16; o; o >>= 1)
            contrib[j] += __shfl_xor_sync(0xffffffffu, contrib[j], o);
    if ((c & 31) == 0) {
        #pragma unroll
        for (int j = 0; j < 16; j++) part[c >> 5][j] = contrib[j];
    }
    __syncthreads();
    if (c == 0) {
        float lg[16], mx = -1e30f;
        #pragma unroll
        for (int j = 0; j < 16; j++) {
            float v = dlb[j];
            #pragma unroll
            for (int w = 0; w < 8; w++) v += part[w][j];
            lg[j] = v;
            mx = fmaxf(mx, v);
        }
        float sum = 0.f;
        #pragma unroll
        for (int j = 0; j < 16; j++) { lg[j] = expf(lg[j] - mx); sum += lg[j]; }
        float inv = 1.f / sum;
        #pragma unroll
        for (int j = 0; j < 16; j++) probs[j] = lg[j] * inv;
    }
    __syncthreads();
    float acc = 0.f;
    #pragma unroll
    for (int wi = 0; wi < 16; wi++) acc += vals[wi] * probs[wi];
    xdlf[(size_t)bx*CH + c] = __float2half(acc);
}

// ----------------------------------------------------------------------------
// Fused axial attention (both axes, atomicAdd into pre-zeroed xg32)
// ----------------------------------------------------------------------------
__global__ void axial_fused(const float* __restrict__ Q,
                            const float* __restrict__ K,
                            const float* __restrict__ V,
                            const float* __restrict__ gsp,
                            const float* __restrict__ gbp,
                            float* __restrict__ out32)
{
    __shared__ float sQ[16][CH];
    __shared__ float sK[16][CH];
    __shared__ float sc[16][17];
    const int axis = blockIdx.y;
    const int blk = blockIdx.x;
    const int b = blk >> 4, f = blk & 15;
    const int t = threadIdx.x;

    for (int idx = t; idx < 16*CH; idx += 256) {
        int i = idx >> 8, c = idx & 255;
        size_t tok = (axis == 0) ? (size_t)((b*16 + f)*16 + i)
                                 : (size_t)((b*16 + i)*16 + f);
        sQ[i][c] = Q[tok*CH + c];
        sK[i][c] = K[tok*CH + c];
    }
    __syncthreads();

    {
        int w = t >> 4, v = t & 15;
        float dot = 0.f;
        #pragma unroll 8
        for (int c = 0; c < CH; c++) dot += sQ[w][c] * sK[v][c];
        float gs = gsp[0], gb0 = gbp[0];
        float d2 = (float)((v - w) * (v - w));
        sc[w][v] = dot - (gs * d2 + gb0);
    }
    __syncthreads();
    if (t < 16) {
        float mx = -1e30f;
        #pragma unroll
        for (int v = 0; v < 16; v++) mx = fmaxf(mx, sc[t][v]);
        float sum = 0.f;
        #pragma unroll
        for (int v = 0; v < 16; v++) { float e = expf(sc[t][v] - mx); sc[t][v] = e; sum += e; }
        float inv = 1.f / sum;
        #pragma unroll
        for (int v = 0; v < 16; v++) sc[t][v] *= inv;
    }
    __syncthreads();

    const int d = t;
    float acc[16] = {};
    #pragma unroll
    for (int v = 0; v < 16; v++) {
        size_t tokv = (axis == 0) ? (size_t)((b*16 + f)*16 + v)
                                  : (size_t)((b*16 + v)*16 + f);
        float vv = V[tokv*CH + d];
        #pragma unroll
        for (int w = 0; w < 16; w++) acc[w] += sc[w][v] * vv;
    }
    #pragma unroll
    for (int w = 0; w < 16; w++) {
        size_t tokw = (axis == 0) ? (size_t)((b*16 + f)*16 + w)
                                  : (size_t)((b*16 + w)*16 + f);
        atomicAdd(&out32[tokw*CH + d], acc[w]);
    }
}

__global__ void xg32toh(const float4* __restrict__ X, __half* __restrict__ Xh)
{
    const size_t i = (size_t)blockIdx.x * 256 + threadIdx.x;
    float4 v = X[i];
    __half2 a = __floats2half2_rn(v.x, v.y), b = __floats2half2_rn(v.z, v.w);
    uint2 p;
    p.x = *(uint32_t*)&a; p.y = *(uint32_t*)&b;
    *(uint2*)(Xh + i * 4) = p;
}

// ----------------------------------------------------------------------------
// Blend
// ----------------------------------------------------------------------------
__global__ void zblend_kernel(const __half2* __restrict__ S0,
                              const __half2* __restrict__ S1,
                              const __half2* __restrict__ S2,
                              const float* __restrict__ wts,
                              __half2* __restrict__ Zb)
{
    const size_t i = (size_t)blockIdx.x * 256 + threadIdx.x;
    const int pix = (int)(i >> 7);
    const float w0 = wts[pix*3+0], w1 = wts[pix*3+1], w2 = wts[pix*3+2];
    float2 a = __half22float2(S0[i]);
    float2 b = __half22float2(S1[i]);
    float2 c = __half22float2(S2[i]);
    Zb[i] = __floats2half2_rn(w0*a.x + w1*b.x + w2*c.x,
                              w0*a.y + w1*b.y + w2*c.y);
}

// ----------------------------------------------------------------------------
// Host launch — round-12 DAG (best known) with fused conversion launch
// ----------------------------------------------------------------------------
extern "C" void kernel_launch(void* const* d_in, const int* in_sizes, int n_in,
                              void* d_out, int out_size)
{
    const float* x      = (const float*)d_in[0];
    const float* attn_w = (const float*)d_in[1];
    const float* attn_b = (const float*)d_in[2];
    const float* edge_w = (const float*)d_in[3];
    const float* mlp_w1 = (const float*)d_in[4];
    const float* mlp_b1 = (const float*)d_in[5];
    const float* mlp_w2 = (const float*)d_in[6];
    const float* mlp_b2 = (const float*)d_in[7];
    const float* dl_w   = (const float*)d_in[8];
    const float* dl_b   = (const float*)d_in[9];
    const float* ax_w   = (const float*)d_in[10];
    const float* ax_b   = (const float*)d_in[11];
    const float* g_sh   = (const float*)d_in[12];
    const float* g_bi   = (const float*)d_in[13];
    const float* sq_w   = (const float*)d_in[14];
    const float* sq_b   = (const float*)d_in[15];
    float* out = (float*)d_out;

    __half *QKVh, *CTXh, *Sh, *Xf, *Zbp, *Wf, *XDLf, *XGH;
    float *T9b, *EDGEb, *WTSb, *AQb, *AKb, *AVb, *XG32, *Yb, *ZB0;
    cudaGetSymbolAddress((void**)&QKVh, g_QKV);
    cudaGetSymbolAddress((void**)&CTXh, g_CTX);
    cudaGetSymbolAddress((void**)&Sh,   g_S);
    cudaGetSymbolAddress((void**)&Xf,   g_xf);
    cudaGetSymbolAddress((void**)&Zbp,  g_Zb);
    cudaGetSymbolAddress((void**)&Wf,   g_Wf);
    cudaGetSymbolAddress((void**)&XDLf, g_xdlf);
    cudaGetSymbolAddress((void**)&XGH,  g_xgh);
    cudaGetSymbolAddress((void**)&T9b,  g_t9);
    cudaGetSymbolAddress((void**)&EDGEb,g_edge);
    cudaGetSymbolAddress((void**)&WTSb, g_wts);
    cudaGetSymbolAddress((void**)&AQb,  g_aQ);
    cudaGetSymbolAddress((void**)&AKb,  g_aK);
    cudaGetSymbolAddress((void**)&AVb,  g_aV);
    cudaGetSymbolAddress((void**)&XG32, g_xg32);
    cudaGetSymbolAddress((void**)&Yb,   g_y);
    cudaGetSymbolAddress((void**)&ZB0,  g_zerob);

    cudaStream_t s_aux;
    cudaStreamCreateWithFlags(&s_aux, cudaStreamNonBlocking);
    cudaEvent_t evX, evE, evS1, evY;
    cudaEventCreateWithFlags(&evX,  cudaEventDisableTiming);
    cudaEventCreateWithFlags(&evE,  cudaEventDisableTiming);
    cudaEventCreateWithFlags(&evS1, cudaEventDisableTiming);
    cudaEventCreateWithFlags(&evY,  cudaEventDisableTiming);

    // ---- main: fused conversions (x -> fp16 and weights -> fp16, one launch) ----
    conv_fused<<<XB + WB, 256>>>((const float4*)x, Xf, attn_w, ax_w, sq_w, Wf);
    cudaEventRecord(evX, 0);

    // ---- aux: edge-selector path (forked after main event; capture-legal) ----
    cudaStreamWaitEvent(s_aux, evX, 0);
    conv9_kernel<<<NTOK/32, 256, 0, s_aux>>>(Xf, edge_w, T9b);
    edge_stencil_kernel<<<NTOK/256, 256, 0, s_aux>>>(T9b, EDGEb);
    wts_kernel<<<NTOK/256, 256, 0, s_aux>>>(EDGEb, mlp_w1, mlp_b1, mlp_w2, mlp_b2, WTSb);
    cudaEventRecord(evE, s_aux);

    // ---- main: fused QKV projections (9 matrices, one launch) ----
    {
        TilesT<__half, 9> Tq;
        for (int br = 0; br < 3; br++)
            for (int j = 0; j < 3; j++) {
                const int s = br*3 + j;
                Tq.t[s].a = Xf;
                Tq.t[s].b = Wf + (size_t)(br*4 + j)*65536;
                Tq.t[s].bias = attn_b + (br*4 + j)*CH;
                Tq.t[s].out  = QKVh + (size_t)s*NTOK*CH;
            }
        gemm_h<<<dim3(18, NTOK/128), 256, GEMM_SMEM>>>(Tq, 256);
    }

    // ---- main: window attention (all branches, one launch) ----
    winattn_all<<<dim3(1024, 12), 128>>>(QKVh, CTXh);

    // ---- main: out-proj S1 first ----
    {
        TilesT<__half, 1> To;
        To.t[0].a = CTXh + (size_t)1*NTOK*CH;
        To.t[0].b = Wf + (size_t)(1*4 + 3)*65536;
        To.t[0].bias = attn_b + (1*4 + 3)*CH;
        To.t[0].out  = Sh + (size_t)1*NTOK*CH;
        gemm_h<<<dim3(2, NTOK/128), 256, GEMM_SMEM>>>(To, 256);
    }
    cudaEventRecord(evS1, 0);

    // ---- aux: pooled/axial chain (hidden under S0/S2 out-proj + zblend) ----
    cudaStreamWaitEvent(s_aux, evS1, 0);
    dlight_kernel<<<NDTOK, 256, 0, s_aux>>>(Sh + (size_t)1*NTOK*CH, dl_w, dl_b, XDLf);
    {
        TilesT<float, 3> Ta;
        float* aqkv[3] = {AQb, AKb, AVb};
        for (int m = 0; m < 3; m++) {
            Ta.t[m].a = XDLf;
            Ta.t[m].b = Wf + WF_AX + (size_t)m*65536;
            Ta.t[m].bias = ax_b + m*CH;
            Ta.t[m].out  = aqkv[m];
        }
        gemm_h<<<dim3(6, NDTOK/128), 256, GEMM_SMEM, s_aux>>>(Ta, 256);
    }
    cudaMemsetAsync(XG32, 0, (size_t)NDTOK*CH*sizeof(float), s_aux);
    axial_fused<<<dim3(BSZ*PP, 2), 256, 0, s_aux>>>(AQb, AKb, AVb, g_sh, g_bi, XG32);
    xg32toh<<<NDTOK*CH/4/256, 256, 0, s_aux>>>((const float4*)XG32, XGH);
    {
        TilesT<float, 1> Ty;
        Ty.t[0].a = XGH;
        Ty.t[0].b = Wf + WF_SQ1;
        Ty.t[0].bias = ZB0;
        Ty.t[0].out  = Yb;
        gemm_h<<<dim3(2, NDTOK/128), 256, GEMM_SMEM, s_aux>>>(Ty, 256);
    }
    cudaEventRecord(evY, s_aux);

    // ---- main: out-proj S0 + S2 (concurrent with aux pooled chain) ----
    {
        TilesT<__half, 2> To;
        const int brs[2] = {0, 2};
        for (int i = 0; i < 2; i++) {
            const int br = brs[i];
            To.t[i].a = CTXh + (size_t)br*NTOK*CH;
            To.t[i].b = Wf + (size_t)(br*4 + 3)*65536;
            To.t[i].bias = attn_b + (br*4 + 3)*CH;
            To.t[i].out  = Sh + (size_t)br*NTOK*CH;
        }
        gemm_h<<<dim3(4, NTOK/128), 256, GEMM_SMEM>>>(To, 256);
    }

    // ---- main: blend (filler while waiting for aux chain) ----
    cudaStreamWaitEvent(0, evE, 0);
    zblend_kernel<<<NTOK*CH/2/256, 256>>>(
        (const __half2*)(Sh + (size_t)0*NTOK*CH),
        (const __half2*)(Sh + (size_t)1*NTOK*CH),
        (const __half2*)(Sh + (size_t)2*NTOK*CH),
        WTSb, (__half2*)Zbp);

    // ---- main: final ----
    cudaStreamWaitEvent(0, evY, 0);
    gemm_up<<<dim3(2, NTOK/128), 256, GEMM_SMEM>>>(Zbp, Wf + WF_SQ2, sq_b, Yb, out);

    cudaEventDestroy(evX);
    cudaEventDestroy(evE);
    cudaEventDestroy(evS1);
    cudaEventDestroy(evY);
    cudaStreamDestroy(s_aux);
}

// round 16
// speedup vs baseline: 1.0078x; 1.0021x over previous
#include <cuda_runtime.h>
#include <cuda_fp16.h>
#include <math.h>
#include <stdint.h>

// ----------------------------------------------------------------------------
// Problem constants
// ----------------------------------------------------------------------------
#define BSZ   16
#define HIMG  64
#define WIMG  64
#define CH    256
#define NTOK  (BSZ*HIMG*WIMG)       // 65536
#define NHEAD 8
#define HS    32
#define PP    16
#define NDTOK (BSZ*PP*PP)           // 4096

// fp16 weight slots ([N][K]): 12 attn + 3 axial + sq1 + sq2
#define WF_ATTN 0
#define WF_AX   (12*65536)
#define WF_SQ1  (15*65536)
#define WF_SQ2  (16*65536)
#define WFTOT   (17*65536)

// ----------------------------------------------------------------------------
// Scratch
// ----------------------------------------------------------------------------
__device__ __half g_QKV[9][NTOK*CH];
__device__ __half g_CTX[3][NTOK*CH];
__device__ __half g_S[3][NTOK*CH];
__device__ __half g_xf[NTOK*CH];
__device__ __half g_Zb[NTOK*CH];
__device__ __half g_Wf[WFTOT];
__device__ __half g_xdlf[NDTOK*CH];
__device__ __half g_xgh[NDTOK*CH];
__device__ float  g_y[NDTOK*CH];
__device__ float  g_zerob[CH];
__device__ float  g_t9[NTOK*9];
__device__ float  g_edge[NTOK];
__device__ float  g_wts[NTOK*3];
__device__ float  g_aQ[NDTOK*CH];
__device__ float  g_aK[NDTOK*CH];
__device__ float  g_aV[NDTOK*CH];
__device__ float  g_xg32[NDTOK*CH];

// ----------------------------------------------------------------------------
// PTX helpers
// ----------------------------------------------------------------------------
__device__ __forceinline__ uint32_t smem_u32(const void* p) {
    uint32_t a;
    asm("{ .reg .u64 t; cvta.to.shared.u64 t, %1; cvt.u32.u64 %0, t; }"
        : "=r"(a) : "l"(p));
    return a;
}
__device__ __forceinline__ void ldsm4(uint32_t* r, uint32_t addr) {
    asm volatile("ldmatrix.sync.aligned.m8n8.x4.shared.b16 {%0,%1,%2,%3}, [%4];"
                 : "=r"(r[0]), "=r"(r[1]), "=r"(r[2]), "=r"(r[3]) : "r"(addr));
}
__device__ __forceinline__ void mma_f16(float* d, const uint32_t* a,
                                        uint32_t b0, uint32_t b1) {
    asm volatile("mma.sync.aligned.m16n8k16.row.col.f32.f16.f16.f32 "
                 "{%0,%1,%2,%3}, {%4,%5,%6,%7}, {%8,%9}, {%0,%1,%2,%3};"
                 : "+f"(d[0]), "+f"(d[1]), "+f"(d[2]), "+f"(d[3])
                 : "r"(a[0]), "r"(a[1]), "r"(a[2]), "r"(a[3]), "r"(b0), "r"(b1));
}
#define CP16(dst, src) \
    asm volatile("cp.async.cg.shared.global [%0], [%1], 16;" :: "r"(dst), "l"(src))
#define CP_COMMIT() asm volatile("cp.async.commit_group;" ::: "memory")
#define CP_WAIT1()  asm volatile("cp.async.wait_group 1;" ::: "memory")
#define CP_WAIT0()  asm volatile("cp.async.wait_group 0;" ::: "memory")

__device__ __forceinline__ void u4_to_f4x2(uint4 r, float4& a, float4& b) {
    __half2 h0 = *(__half2*)&r.x, h1 = *(__half2*)&r.y;
    __half2 h2 = *(__half2*)&r.z, h3 = *(__half2*)&r.w;
    float2 f0 = __half22float2(h0), f1 = __half22float2(h1);
    float2 f2 = __half22float2(h2), f3 = __half22float2(h3);
    a = make_float4(f0.x, f0.y, f1.x, f1.y);
    b = make_float4(f2.x, f2.y, f3.x, f3.y);
}
__device__ __forceinline__ uint4 f4x2_to_u4(float4 a, float4 b) {
    __half2 h0 = __floats2half2_rn(a.x, a.y), h1 = __floats2half2_rn(a.z, a.w);
    __half2 h2 = __floats2half2_rn(b.x, b.y), h3 = __floats2half2_rn(b.z, b.w);
    uint4 r;
    r.x = *(uint32_t*)&h0; r.y = *(uint32_t*)&h1;
    r.z = *(uint32_t*)&h2; r.w = *(uint32_t*)&h3;
    return r;
}
__device__ __forceinline__ void store2(float* p, float a, float b) {
    *(float2*)p = make_float2(a, b);
}
__device__ __forceinline__ void store2(__half* p, float a, float b) {
    *(__half2*)p = __floats2half2_rn(a, b);
}

// ----------------------------------------------------------------------------
// fp16 GEMM: round-7 tile (128x128, 8 warps 4Mx2N), now 3-stage cp.async ring
// with a single __syncthreads per chunk.
// ----------------------------------------------------------------------------
template<typename OT> struct TileT {
    const __half *a, *b;
    const float* bias;
    OT* out;
};
template<typename OT, int NM> struct TilesT { TileT<OT> t[NM]; };

#define SMH_A   0
#define SMH_B   10240
#define SMH_BUF 20480
#define GEMM_SMEM3 (3*SMH_BUF)   // 61440 (needs attribute)
#define GEMM_SMEM2 (2*SMH_BUF)   // 40960 (gemm_up)

template<typename OT>
__device__ __forceinline__ void load_chunkh(
    uint32_t sbase, const TileT<OT>& e, int K, int row0, int col0, int k0, int t)
{
    const int lrow = t >> 1;
    const int lseg = (t & 1) * 16;
    const uint32_t doff = (uint32_t)(lrow * 80 + lseg * 2);
    const __half* s = e.a + (size_t)(row0 + lrow) * K + k0 + lseg;
    CP16(sbase + SMH_A + doff,      s);
    CP16(sbase + SMH_A + doff + 16, s + 8);
    s = e.b + (size_t)(col0 + lrow) * K + k0 + lseg;
    CP16(sbase + SMH_B + doff,      s);
    CP16(sbase + SMH_B + doff + 16, s + 8);
}

template<typename OT, int NM>
__global__ __launch_bounds__(256)
void gemm_h(TilesT<OT, NM> T, int K)
{
    extern __shared__ char sm[];
    const uint32_t sb0 = smem_u32(sm);

    const int t = threadIdx.x;
    const int wid = t >> 5, lane = t & 31;
    const TileT<OT> e = T.t[blockIdx.x >> 1];
    const int col0 = (blockIdx.x & 1) * 128;
    const int row0 = blockIdx.y * 128;
    const int mw = wid & 3;
    const int nw = wid >> 2;
    const int NC = K >> 5;

    float acc[2][8][4];
    #pragma unroll
    for (int i = 0; i < 2; i++)
        #pragma unroll
        for (int j = 0; j < 8; j++)
            #pragma unroll
            for (int q = 0; q < 4; q++) acc[i][j][q] = 0.f;

    // prologue: stages 0, 1
    load_chunkh(sb0, e, K, row0, col0, 0, t);
    CP_COMMIT();
    if (NC > 1) {
        load_chunkh(sb0 + SMH_BUF, e, K, row0, col0, 32, t);
        CP_COMMIT();
    }

    const uint32_t a_off[2] = {
        (uint32_t)((mw*32 + 0*16 + (lane & 15)) * 80),
        (uint32_t)((mw*32 + 1*16 + (lane & 15)) * 80)
    };
    const uint32_t a_col = (uint32_t)(((lane >> 4) << 3) * 2);
    uint32_t b_off[4];
    #pragma unroll
    for (int j = 0; j < 4; j++)
        b_off[j] = (uint32_t)((nw*64 + j*16 + (lane & 7) + ((lane >> 4) << 3)) * 80);
    const uint32_t b_col = (uint32_t)((((lane >> 3) & 1) << 3) * 2);

    int buf = 0;
    for (int c = 0; c < NC; c++) {
        if (c + 1 < NC) CP_WAIT1(); else CP_WAIT0();
        __syncthreads();   // all warps done with buf (c-1)%3 compute; chunk c visible
        if (c + 2 < NC) {
            const int nb = (buf + 2 >= 3) ? buf - 1 : buf + 2;
            load_chunkh(sb0 + (uint32_t)nb * SMH_BUF, e, K, row0, col0,
                        (c + 2) << 5, t);
            CP_COMMIT();
        }
        const uint32_t bb = sb0 + (uint32_t)buf * SMH_BUF;

        #pragma unroll
        for (int ks = 0; ks < 2; ks++) {
            const uint32_t kc = (uint32_t)(ks * 32);
            uint32_t af[2][4], bf[4][4];
            #pragma unroll
            for (int mt = 0; mt < 2; mt++)
                ldsm4(af[mt], bb + SMH_A + a_off[mt] + kc + a_col);
            #pragma unroll
            for (int j = 0; j < 4; j++)
                ldsm4(bf[j], bb + SMH_B + b_off[j] + kc + b_col);
            #pragma unroll
            for (int mt = 0; mt < 2; mt++)
                #pragma unroll
                for (int j = 0; j < 4; j++) {
                    mma_f16(acc[mt][2*j],     af[mt], bf[j][0], bf[j][1]);
                    mma_f16(acc[mt][2*j + 1], af[mt], bf[j][2], bf[j][3]);
                }
        }
        buf = (buf + 1 == 3) ? 0 : buf + 1;
    }

    #pragma unroll
    for (int mt = 0; mt < 2; mt++) {
        const int r_ = row0 + mw*32 + mt*16 + (lane >> 2);
        #pragma unroll
        for (int j = 0; j < 8; j++) {
            const int c_ = col0 + nw*64 + j*8 + (lane & 3)*2;
            const float b0 = e.bias[c_], b1 = e.bias[c_ + 1];
            store2(&e.out[(size_t)r_ * 256 + c_],       acc[mt][j][0] + b0, acc[mt][j][1] + b1);
            store2(&e.out[(size_t)(r_ + 8) * 256 + c_], acc[mt][j][2] + b0, acc[mt][j][3] + b1);
        }
    }
}

// ----------------------------------------------------------------------------
// Final GEMM (2-stage, unchanged): out = Zb @ W2^T + sq_b + bilerp(y)
// ----------------------------------------------------------------------------
__global__ __launch_bounds__(256)
void gemm_up(const __half* __restrict__ A, const __half* __restrict__ B,
             const float* __restrict__ bias, const float* __restrict__ y,
             float* __restrict__ Cm)
{
    extern __shared__ char sm[];
    const uint32_t sb0 = smem_u32(sm);

    const int t = threadIdx.x;
    const int wid = t >> 5, lane = t & 31;
    const int col0 = (blockIdx.x & 1) * 128;
    const int row0 = blockIdx.y * 128;
    const int mw = wid & 3;
    const int nw = wid >> 2;
    const int NC = 8;
    const int K = 256;

    TileT<float> e;
    e.a = A; e.b = B; e.bias = bias; e.out = Cm;

    float acc[2][8][4];
    #pragma unroll
    for (int i = 0; i < 2; i++)
        #pragma unroll
        for (int j = 0; j < 8; j++)
            #pragma unroll
            for (int q = 0; q < 4; q++) acc[i][j][q] = 0.f;

    load_chunkh(sb0, e, K, row0, col0, 0, t);
    CP_COMMIT();

    const uint32_t a_off[2] = {
        (uint32_t)((mw*32 + 0*16 + (lane & 15)) * 80),
        (uint32_t)((mw*32 + 1*16 + (lane & 15)) * 80)
    };
    const uint32_t a_col = (uint32_t)(((lane >> 4) << 3) * 2);
    uint32_t b_off[4];
    #pragma unroll
    for (int j = 0; j < 4; j++)
        b_off[j] = (uint32_t)((nw*64 + j*16 + (lane & 7) + ((lane >> 4) << 3)) * 80);
    const uint32_t b_col = (uint32_t)((((lane >> 3) & 1) << 3) * 2);

    for (int c = 0; c < NC; c++) {
        CP_WAIT0();
        __syncthreads();
        if (c + 1 < NC) {
            load_chunkh(sb0 + (uint32_t)((c + 1) & 1) * SMH_BUF, e, K, row0, col0,
                        (c + 1) << 5, t);
            CP_COMMIT();
        }
        const uint32_t bb = sb0 + (uint32_t)(c & 1) * SMH_BUF;

        #pragma unroll
        for (int ks = 0; ks < 2; ks++) {
            const uint32_t kc = (uint32_t)(ks * 32);
            uint32_t af[2][4], bf[4][4];
            #pragma unroll
            for (int mt = 0; mt < 2; mt++)
                ldsm4(af[mt], bb + SMH_A + a_off[mt] + kc + a_col);
            #pragma unroll
            for (int j = 0; j < 4; j++)
                ldsm4(bf[j], bb + SMH_B + b_off[j] + kc + b_col);
            #pragma unroll
            for (int mt = 0; mt < 2; mt++)
                #pragma unroll
                for (int j = 0; j < 4; j++) {
                    mma_f16(acc[mt][2*j],     af[mt], bf[j][0], bf[j][1]);
                    mma_f16(acc[mt][2*j + 1], af[mt], bf[j][2], bf[j][3]);
                }
        }
        __syncthreads();
    }

    const float scl = 15.f / 63.f;
    #pragma unroll
    for (int mt = 0; mt < 2; mt++) {
        #pragma unroll
        for (int hh = 0; hh < 2; hh++) {
            const int pix = row0 + mw*32 + mt*16 + (lane >> 2) + hh*8;
            const int bimg = pix >> 12, yy = (pix >> 6) & 63, xx = pix & 63;
            float pr = yy * scl;
            int r0 = (int)floorf(pr);
            float tr = pr - (float)r0;
            int r1 = min(r0 + 1, 15);
            float pc = xx * scl;
            int c0i = (int)floorf(pc);
            float tc = pc - (float)c0i;
            int c1i = min(c0i + 1, 15);
            const float* yb = y + (size_t)bimg * 256 * CH;
            const float* y00 = yb + (r0*16 + c0i)*CH;
            const float* y01 = yb + (r0*16 + c1i)*CH;
            const float* y10 = yb + (r1*16 + c0i)*CH;
            const float* y11 = yb + (r1*16 + c1i)*CH;
            const float w00 = (1.f-tr)*(1.f-tc), w01 = (1.f-tr)*tc;
            const float w10 = tr*(1.f-tc),       w11 = tr*tc;
            #pragma unroll
            for (int j = 0; j < 8; j++) {
                const int c_ = col0 + nw*64 + j*8 + (lane & 3)*2;
                float2 v00 = *(const float2*)&y00[c_];
                float2 v01 = *(const float2*)&y01[c_];
                float2 v10 = *(const float2*)&y10[c_];
                float2 v11 = *(const float2*)&y11[c_];
                float up0 = w00*v00.x + w01*v01.x + w10*v10.x + w11*v11.x;
                float up1 = w00*v00.y + w01*v01.y + w10*v10.y + w11*v11.y;
                const float a0 = acc[mt][j][hh*2 + 0], a1 = acc[mt][j][hh*2 + 1];
                store2(&Cm[(size_t)pix * 256 + c_],
                       a0 + bias[c_] + up0, a1 + bias[c_ + 1] + up1);
            }
        }
    }
}

// ----------------------------------------------------------------------------
// Fused conversions: blocks [0, XB) do x->fp16; blocks [XB, XB+WB) do weights
// ----------------------------------------------------------------------------
#define XB (NTOK*CH/4/256)      // 16384
#define WB (17*65536/256)       // 4352

__global__ void conv_fused(const float4* __restrict__ X, __half* __restrict__ Xf,
                           const float* __restrict__ attn_w,
                           const float* __restrict__ ax_w,
                           const float* __restrict__ sq_w,
                           __half* __restrict__ Wf)
{
    if (blockIdx.x < XB) {
        const size_t i = (size_t)blockIdx.x * 256 + threadIdx.x;
        float4 v = X[i];
        __half2 a = __floats2half2_rn(v.x, v.y), b = __floats2half2_rn(v.z, v.w);
        uint2 p;
        p.x = *(uint32_t*)&a; p.y = *(uint32_t*)&b;
        *(uint2*)(Xf + i * 4) = p;
    } else {
        const int idx = (blockIdx.x - XB) * 256 + threadIdx.x;
        const int m = idx >> 16, r = idx & 65535;
        if (m < 15) {
            const int k = r >> 8, n = r & 255;
            const float w = (m < 12) ? attn_w[idx] : ax_w[(m - 12)*65536 + r];
            Wf[((size_t)m << 16) + (n << 8) + k] = __float2half(w);
        } else {
            const int o = r >> 8, k = r & 255;
            const int half_ = m - 15;
            Wf[((size_t)m << 16) + r] = __float2half(sq_w[o*512 + half_*256 + k]);
        }
    }
}

// ----------------------------------------------------------------------------
// Window attention: all 3 branches in one launch. grid (1024, 12), block 128.
// ----------------------------------------------------------------------------
template<int WS>
__device__ __forceinline__ void winattn_body(
    const uint4* __restrict__ Q8, const uint4* __restrict__ K8,
    const uint4* __restrict__ V8, uint4* __restrict__ C8,
    float4 (*sK)[9], float4 (*sV)[9], int head, int bx, int tt)
{
    constexpr int WIN = WS*WS;
    constexpr int G   = 64 / WIN;
    constexpr int NW  = HIMG / WS;
    const int g  = tt / WIN;
    const int qi = tt % WIN;
    const int widx = bx * G + g;
    const int b   = widx / (NW*NW);
    const int rem = widx % (NW*NW);
    const int p1 = rem / NW, p2 = rem % NW;
    const int r  = p1*WS + qi/WS;
    const int cc = p2*WS + qi%WS;
    const int token = (b*HIMG + r)*WIMG + cc;
    const size_t base8 = (size_t)token*(CH/8) + head*(HS/8);

    float4 q[8];
    #pragma unroll
    for (int d = 0; d < 4; d++) {
        u4_to_f4x2(Q8[base8 + d], q[2*d], q[2*d + 1]);
        float4 ka, kb, va, vb;
        u4_to_f4x2(K8[base8 + d], ka, kb);
        u4_to_f4x2(V8[base8 + d], va, vb);
        sK[tt][2*d] = ka; sK[tt][2*d + 1] = kb;
        sV[tt][2*d] = va; sV[tt][2*d + 1] = vb;
    }
    __syncthreads();

    const float scale = 0.17677669529663687f;
    float sc[WIN];
    float mx = -1e30f;
    #pragma unroll
    for (int v = 0; v < WIN; v++) {
        float dot = 0.f;
        #pragma unroll
        for (int d = 0; d < 8; d++) {
            float4 k4 = sK[g*WIN + v][d];
            dot += q[d].x*k4.x + q[d].y*k4.y + q[d].z*k4.z + q[d].w*k4.w;
        }
        dot *= scale;
        sc[v] = dot;
        mx = fmaxf(mx, dot);
    }
    float sum = 0.f;
    #pragma unroll
    for (int v = 0; v < WIN; v++) { sc[v] = expf(sc[v] - mx); sum += sc[v]; }
    const float inv = 1.f / sum;
    #pragma unroll
    for (int v = 0; v < WIN; v++) sc[v] *= inv;

    #pragma unroll
    for (int dd = 0; dd < 4; dd++) {
        float4 a0 = make_float4(0.f, 0.f, 0.f, 0.f);
        float4 a1 = make_float4(0.f, 0.f, 0.f, 0.f);
        #pragma unroll
        for (int v = 0; v < WIN; v++) {
            float4 v0 = sV[g*WIN + v][2*dd];
            float4 v1 = sV[g*WIN + v][2*dd + 1];
            a0.x += sc[v]*v0.x; a0.y += sc[v]*v0.y;
            a0.z += sc[v]*v0.z; a0.w += sc[v]*v0.w;
            a1.x += sc[v]*v1.x; a1.y += sc[v]*v1.y;
            a1.z += sc[v]*v1.z; a1.w += sc[v]*v1.w;
        }
        C8[base8 + dd] = f4x2_to_u4(a0, a1);
    }
}

__global__ __launch_bounds__(128)
void winattn_all(const __half* __restrict__ QKVbase, __half* __restrict__ CTXbase)
{
    __shared__ float4 sK[2][64][9];
    __shared__ float4 sV[2][64][9];
    const int t = threadIdx.x, slot = t >> 6, tt = t & 63;
    const int br = blockIdx.y >> 2, hp = blockIdx.y & 3;
    const int head = hp*2 + slot;
    const uint4* Q8 = (const uint4*)(QKVbase + (size_t)(br*3 + 0)*NTOK*CH);
    const uint4* K8 = (const uint4*)(QKVbase + (size_t)(br*3 + 1)*NTOK*CH);
    const uint4* V8 = (const uint4*)(QKVbase + (size_t)(br*3 + 2)*NTOK*CH);
    uint4* C8 = (uint4*)(CTXbase + (size_t)br*NTOK*CH);
    if (br == 0)      winattn_body<2>(Q8, K8, V8, C8, sK[slot], sV[slot], head, blockIdx.x, tt);
    else if (br == 1) winattn_body<4>(Q8, K8, V8, C8, sK[slot], sV[slot], head, blockIdx.x, tt);
    else              winattn_body<8>(Q8, K8, V8, C8, sK[slot], sV[slot], head, blockIdx.x, tt);
}

// ----------------------------------------------------------------------------
// Edge selector
// ----------------------------------------------------------------------------
__global__ void conv9_kernel(const __half* __restrict__ x,
                             const float* __restrict__ ew,
                             float* __restrict__ t9)
{
    __shared__ float sw[CH*9];
    const int tid = threadIdx.x;
    for (int i = tid; i < CH*9; i += 256) sw[i] = ew[i];
    __syncthreads();

    const int warp = tid >> 5, lane = tid & 31;
    #pragma unroll
    for (int pp = 0; pp < 4; pp++) {
        const int pix = blockIdx.x * 32 + warp * 4 + pp;
        const uint4 v = ((const uint4*)(x + (size_t)pix*CH))[lane];
        float4 fa, fb;
        u4_to_f4x2(v, fa, fb);
        float xa[8] = {fa.x, fa.y, fa.z, fa.w, fb.x, fb.y, fb.z, fb.w};

        float acc[9] = {};
        #pragma unroll
        for (int i = 0; i < 8; i++) {
            const int c = lane*8 + i;
            #pragma unroll
            for (int k = 0; k < 9; k++) acc[k] += xa[i] * sw[c*9 + k];
        }
        #pragma unroll
        for (int k = 0; k < 9; k++)
            #pragma unroll
            for (int o = 16; o; o >>= 1)
                acc[k] += __shfl_xor_sync(0xffffffffu, acc[k], o);
        if (lane < 9) t9[(size_t)pix*9 + lane] = acc[lane];
    }
}

__global__ void edge_stencil_kernel(const float* __restrict__ t9,
                                    float* __restrict__ edge)
{
    const int pix = blockIdx.x * 256 + threadIdx.x;
    const int b = pix >> 12, y = (pix >> 6) & 63, xx = pix & 63;
    float s = 0.f;
    #pragma unroll
    for (int ky = 0; ky < 3; ky++) {
        const int yy = y + ky - 1;
        if (yy < 0 || yy > 63) continue;
        #pragma unroll
        for (int kx = 0; kx < 3; kx++) {
            const int xw = xx + kx - 1;
            if (xw < 0 || xw > 63) continue;
            s += t9[(size_t)((b*64 + yy)*64 + xw)*9 + ky*3 + kx];
        }
    }
    edge[pix] = fabsf(s);
}

__global__ void wts_kernel(const float* __restrict__ edge,
                           const float* __restrict__ w1, const float* __restrict__ b1,
                           const float* __restrict__ w2, const float* __restrict__ b2,
                           float* __restrict__ wts)
{
    int pix = blockIdx.x * blockDim.x + threadIdx.x;
    if (pix >= NTOK) return;
    int b = pix >> 12, y = (pix >> 6) & 63, xx = pix & 63;
    float s = 0.f;
    for (int dy = -1; dy <= 1; dy++) {
        int yy = y + dy; if (yy < 0 || yy > 63) continue;
        for (int dx = -1; dx <= 1; dx++) {
            int xw = xx + dx; if (xw < 0 || xw > 63) continue;
            s += edge[(b*64 + yy)*64 + xw];
        }
    }
    float e = s * (1.f/9.f);
    float lg[3] = {b2[0], b2[1], b2[2]};
    #pragma unroll
    for (int j = 0; j < 16; j++) {
        float h = fmaxf(e * w1[j] + b1[j], 0.f);
        lg[0] += h * w2[j*3 + 0];
        lg[1] += h * w2[j*3 + 1];
        lg[2] += h * w2[j*3 + 2];
    }
    float mx = fmaxf(lg[0], fmaxf(lg[1], lg[2]));
    float e0 = expf(lg[0]-mx), e1 = expf(lg[1]-mx), e2 = expf(lg[2]-mx);
    float inv = 1.f / (e0 + e1 + e2);
    wts[pix*3+0] = e0*inv;
    wts[pix*3+1] = e1*inv;
    wts[pix*3+2] = e2*inv;
}

// ----------------------------------------------------------------------------
// DlightConv
// ----------------------------------------------------------------------------
__global__ void dlight_kernel(const __half* __restrict__ S1,
                              const float* __restrict__ dlw,
                              const float* __restrict__ dlb,
                              __half* __restrict__ xdlf)
{
    __shared__ float part[8][16];
    __shared__ float probs[16];
    const int bx = blockIdx.x;
    const int b = bx >> 8, p1 = (bx >> 4) & 15, p2 = bx & 15;
    const int c = threadIdx.x;

    float vals[16];
    float mean = 0.f;
    #pragma unroll
    for (int wi = 0; wi < 16; wi++) {
        int r = p1*4 + (wi >> 2), cc = p2*4 + (wi & 3);
        vals[wi] = __half2float(S1[((size_t)((b*64 + r)*64 + cc))*CH + c]);
        mean += vals[wi];
    }
    mean *= (1.f/16.f);

    float contrib[16];
    #pragma unroll
    for (int j = 0; j < 16; j++) contrib[j] = mean * dlw[c*16 + j];
    #pragma unroll
    for (int j = 0; j < 16; j++)
        #pragma unroll
        for (int o = 16; o; o >>= 1)
            contrib[j] += __shfl_xor_sync(0xffffffffu, contrib[j], o);
    if ((c & 31) == 0) {
        #pragma unroll
        for (int j = 0; j < 16; j++) part[c >> 5][j] = contrib[j];
    }
    __syncthreads();
    if (c == 0) {
        float lg[16], mx = -1e30f;
        #pragma unroll
        for (int j = 0; j < 16; j++) {
            float v = dlb[j];
            #pragma unroll
            for (int w = 0; w < 8; w++) v += part[w][j];
            lg[j] = v;
            mx = fmaxf(mx, v);
        }
        float sum = 0.f;
        #pragma unroll
        for (int j = 0; j < 16; j++) { lg[j] = expf(lg[j] - mx); sum += lg[j]; }
        float inv = 1.f / sum;
        #pragma unroll
        for (int j = 0; j < 16; j++) probs[j] = lg[j] * inv;
    }
    __syncthreads();
    float acc = 0.f;
    #pragma unroll
    for (int wi = 0; wi < 16; wi++) acc += vals[wi] * probs[wi];
    xdlf[(size_t)bx*CH + c] = __float2half(acc);
}

// ----------------------------------------------------------------------------
// Fused axial attention (both axes, atomicAdd into pre-zeroed xg32)
// ----------------------------------------------------------------------------
__global__ void axial_fused(const float* __restrict__ Q,
                            const float* __restrict__ K,
                            const float* __restrict__ V,
                            const float* __restrict__ gsp,
                            const float* __restrict__ gbp,
                            float* __restrict__ out32)
{
    __shared__ float sQ[16][CH];
    __shared__ float sK[16][CH];
    __shared__ float sc[16][17];
    const int axis = blockIdx.y;
    const int blk = blockIdx.x;
    const int b = blk >> 4, f = blk & 15;
    const int t = threadIdx.x;

    for (int idx = t; idx < 16*CH; idx += 256) {
        int i = idx >> 8, c = idx & 255;
        size_t tok = (axis == 0) ? (size_t)((b*16 + f)*16 + i)
                                 : (size_t)((b*16 + i)*16 + f);
        sQ[i][c] = Q[tok*CH + c];
        sK[i][c] = K[tok*CH + c];
    }
    __syncthreads();

    {
        int w = t >> 4, v = t & 15;
        float dot = 0.f;
        #pragma unroll 8
        for (int c = 0; c < CH; c++) dot += sQ[w][c] * sK[v][c];
        float gs = gsp[0], gb0 = gbp[0];
        float d2 = (float)((v - w) * (v - w));
        sc[w][v] = dot - (gs * d2 + gb0);
    }
    __syncthreads();
    if (t < 16) {
        float mx = -1e30f;
        #pragma unroll
        for (int v = 0; v < 16; v++) mx = fmaxf(mx, sc[t][v]);
        float sum = 0.f;
        #pragma unroll
        for (int v = 0; v < 16; v++) { float e = expf(sc[t][v] - mx); sc[t][v] = e; sum += e; }
        float inv = 1.f / sum;
        #pragma unroll
        for (int v = 0; v < 16; v++) sc[t][v] *= inv;
    }
    __syncthreads();

    const int d = t;
    float acc[16] = {};
    #pragma unroll
    for (int v = 0; v < 16; v++) {
        size_t tokv = (axis == 0) ? (size_t)((b*16 + f)*16 + v)
                                  : (size_t)((b*16 + v)*16 + f);
        float vv = V[tokv*CH + d];
        #pragma unroll
        for (int w = 0; w < 16; w++) acc[w] += sc[w][v] * vv;
    }
    #pragma unroll
    for (int w = 0; w < 16; w++) {
        size_t tokw = (axis == 0) ? (size_t)((b*16 + f)*16 + w)
                                  : (size_t)((b*16 + w)*16 + f);
        atomicAdd(&out32[tokw*CH + d], acc[w]);
    }
}

__global__ void xg32toh(const float4* __restrict__ X, __half* __restrict__ Xh)
{
    const size_t i = (size_t)blockIdx.x * 256 + threadIdx.x;
    float4 v = X[i];
    __half2 a = __floats2half2_rn(v.x, v.y), b = __floats2half2_rn(v.z, v.w);
    uint2 p;
    p.x = *(uint32_t*)&a; p.y = *(uint32_t*)&b;
    *(uint2*)(Xh + i * 4) = p;
}

// ----------------------------------------------------------------------------
// Blend
// ----------------------------------------------------------------------------
__global__ void zblend_kernel(const __half2* __restrict__ S0,
                              const __half2* __restrict__ S1,
                              const __half2* __restrict__ S2,
                              const float* __restrict__ wts,
                              __half2* __restrict__ Zb)
{
    const size_t i = (size_t)blockIdx.x * 256 + threadIdx.x;
    const int pix = (int)(i >> 7);
    const float w0 = wts[pix*3+0], w1 = wts[pix*3+1], w2 = wts[pix*3+2];
    float2 a = __half22float2(S0[i]);
    float2 b = __half22float2(S1[i]);
    float2 c = __half22float2(S2[i]);
    Zb[i] = __floats2half2_rn(w0*a.x + w1*b.x + w2*c.x,
                              w0*a.y + w1*b.y + w2*c.y);
}

// ----------------------------------------------------------------------------
// Host launch — round-15 DAG (best known) with 3-stage gemm_h
// ----------------------------------------------------------------------------
extern "C" void kernel_launch(void* const* d_in, const int* in_sizes, int n_in,
                              void* d_out, int out_size)
{
    const float* x      = (const float*)d_in[0];
    const float* attn_w = (const float*)d_in[1];
    const float* attn_b = (const float*)d_in[2];
    const float* edge_w = (const float*)d_in[3];
    const float* mlp_w1 = (const float*)d_in[4];
    const float* mlp_b1 = (const float*)d_in[5];
    const float* mlp_w2 = (const float*)d_in[6];
    const float* mlp_b2 = (const float*)d_in[7];
    const float* dl_w   = (const float*)d_in[8];
    const float* dl_b   = (const float*)d_in[9];
    const float* ax_w   = (const float*)d_in[10];
    const float* ax_b   = (const float*)d_in[11];
    const float* g_sh   = (const float*)d_in[12];
    const float* g_bi   = (const float*)d_in[13];
    const float* sq_w   = (const float*)d_in[14];
    const float* sq_b   = (const float*)d_in[15];
    float* out = (float*)d_out;

    __half *QKVh, *CTXh, *Sh, *Xf, *Zbp, *Wf, *XDLf, *XGH;
    float *T9b, *EDGEb, *WTSb, *AQb, *AKb, *AVb, *XG32, *Yb, *ZB0;
    cudaGetSymbolAddress((void**)&QKVh, g_QKV);
    cudaGetSymbolAddress((void**)&CTXh, g_CTX);
    cudaGetSymbolAddress((void**)&Sh,   g_S);
    cudaGetSymbolAddress((void**)&Xf,   g_xf);
    cudaGetSymbolAddress((void**)&Zbp,  g_Zb);
    cudaGetSymbolAddress((void**)&Wf,   g_Wf);
    cudaGetSymbolAddress((void**)&XDLf, g_xdlf);
    cudaGetSymbolAddress((void**)&XGH,  g_xgh);
    cudaGetSymbolAddress((void**)&T9b,  g_t9);
    cudaGetSymbolAddress((void**)&EDGEb,g_edge);
    cudaGetSymbolAddress((void**)&WTSb, g_wts);
    cudaGetSymbolAddress((void**)&AQb,  g_aQ);
    cudaGetSymbolAddress((void**)&AKb,  g_aK);
    cudaGetSymbolAddress((void**)&AVb,  g_aV);
    cudaGetSymbolAddress((void**)&XG32, g_xg32);
    cudaGetSymbolAddress((void**)&Yb,   g_y);
    cudaGetSymbolAddress((void**)&ZB0,  g_zerob);

    cudaFuncSetAttribute((const void*)gemm_h<__half, 9>,
                         cudaFuncAttributeMaxDynamicSharedMemorySize, GEMM_SMEM3);
    cudaFuncSetAttribute((const void*)gemm_h<__half, 1>,
                         cudaFuncAttributeMaxDynamicSharedMemorySize, GEMM_SMEM3);
    cudaFuncSetAttribute((const void*)gemm_h<__half, 2>,
                         cudaFuncAttributeMaxDynamicSharedMemorySize, GEMM_SMEM3);
    cudaFuncSetAttribute((const void*)gemm_h<float, 3>,
                         cudaFuncAttributeMaxDynamicSharedMemorySize, GEMM_SMEM3);
    cudaFuncSetAttribute((const void*)gemm_h<float, 1>,
                         cudaFuncAttributeMaxDynamicSharedMemorySize, GEMM_SMEM3);

    cudaStream_t s_aux;
    cudaStreamCreateWithFlags(&s_aux, cudaStreamNonBlocking);
    cudaEvent_t evX, evE, evS1, evY;
    cudaEventCreateWithFlags(&evX,  cudaEventDisableTiming);
    cudaEventCreateWithFlags(&evE,  cudaEventDisableTiming);
    cudaEventCreateWithFlags(&evS1, cudaEventDisableTiming);
    cudaEventCreateWithFlags(&evY,  cudaEventDisableTiming);

    // ---- main: fused conversions ----
    conv_fused<<<XB + WB, 256>>>((const float4*)x, Xf, attn_w, ax_w, sq_w, Wf);
    cudaEventRecord(evX, 0);

    // ---- aux: edge-selector path ----
    cudaStreamWaitEvent(s_aux, evX, 0);
    conv9_kernel<<<NTOK/32, 256, 0, s_aux>>>(Xf, edge_w, T9b);
    edge_stencil_kernel<<<NTOK/256, 256, 0, s_aux>>>(T9b, EDGEb);
    wts_kernel<<<NTOK/256, 256, 0, s_aux>>>(EDGEb, mlp_w1, mlp_b1, mlp_w2, mlp_b2, WTSb);
    cudaEventRecord(evE, s_aux);

    // ---- main: fused QKV projections ----
    {
        TilesT<__half, 9> Tq;
        for (int br = 0; br < 3; br++)
            for (int j = 0; j < 3; j++) {
                const int s = br*3 + j;
                Tq.t[s].a = Xf;
                Tq.t[s].b = Wf + (size_t)(br*4 + j)*65536;
                Tq.t[s].bias = attn_b + (br*4 + j)*CH;
                Tq.t[s].out  = QKVh + (size_t)s*NTOK*CH;
            }
        gemm_h<<<dim3(18, NTOK/128), 256, GEMM_SMEM3>>>(Tq, 256);
    }

    // ---- main: window attention ----
    winattn_all<<<dim3(1024, 12), 128>>>(QKVh, CTXh);

    // ---- main: out-proj S1 first ----
    {
        TilesT<__half, 1> To;
        To.t[0].a = CTXh + (size_t)1*NTOK*CH;
        To.t[0].b = Wf + (size_t)(1*4 + 3)*65536;
        To.t[0].bias = attn_b + (1*4 + 3)*CH;
        To.t[0].out  = Sh + (size_t)1*NTOK*CH;
        gemm_h<<<dim3(2, NTOK/128), 256, GEMM_SMEM3>>>(To, 256);
    }
    cudaEventRecord(evS1, 0);

    // ---- aux: pooled/axial chain ----
    cudaStreamWaitEvent(s_aux, evS1, 0);
    dlight_kernel<<<NDTOK, 256, 0, s_aux>>>(Sh + (size_t)1*NTOK*CH, dl_w, dl_b, XDLf);
    {
        TilesT<float, 3> Ta;
        float* aqkv[3] = {AQb, AKb, AVb};
        for (int m = 0; m < 3; m++) {
            Ta.t[m].a = XDLf;
            Ta.t[m].b = Wf + WF_AX + (size_t)m*65536;
            Ta.t[m].bias = ax_b + m*CH;
            Ta.t[m].out  = aqkv[m];
        }
        gemm_h<<<dim3(6, NDTOK/128), 256, GEMM_SMEM3, s_aux>>>(Ta, 256);
    }
    cudaMemsetAsync(XG32, 0, (size_t)NDTOK*CH*sizeof(float), s_aux);
    axial_fused<<<dim3(BSZ*PP, 2), 256, 0, s_aux>>>(AQb, AKb, AVb, g_sh, g_bi, XG32);
    xg32toh<<<NDTOK*CH/4/256, 256, 0, s_aux>>>((const float4*)XG32, XGH);
    {
        TilesT<float, 1> Ty;
        Ty.t[0].a = XGH;
        Ty.t[0].b = Wf + WF_SQ1;
        Ty.t[0].bias = ZB0;
        Ty.t[0].out  = Yb;
        gemm_h<<<dim3(2, NDTOK/128), 256, GEMM_SMEM3, s_aux>>>(Ty, 256);
    }
    cudaEventRecord(evY, s_aux);

    // ---- main: out-proj S0 + S2 ----
    {
        TilesT<__half, 2> To;
        const int brs[2] = {0, 2};
        for (int i = 0; i < 2; i++) {
            const int br = brs[i];
            To.t[i].a = CTXh + (size_t)br*NTOK*CH;
            To.t[i].b = Wf + (size_t)(br*4 + 3)*65536;
            To.t[i].bias = attn_b + (br*4 + 3)*CH;
            To.t[i].out  = Sh + (size_t)br*NTOK*CH;
        }
        gemm_h<<<dim3(4, NTOK/128), 256, GEMM_SMEM3>>>(To, 256);
    }

    // ---- main: blend (filler while waiting for aux chain) ----
    cudaStreamWaitEvent(0, evE, 0);
    zblend_kernel<<<NTOK*CH/2/256, 256>>>(
        (const __half2*)(Sh + (size_t)0*NTOK*CH),
        (const __half2*)(Sh + (size_t)1*NTOK*CH),
        (const __half2*)(Sh + (size_t)2*NTOK*CH),
        WTSb, (__half2*)Zbp);

    // ---- main: final ----
    cudaStreamWaitEvent(0, evY, 0);
    gemm_up<<<dim3(2, NTOK/128), 256, GEMM_SMEM2>>>(Zbp, Wf + WF_SQ2, sq_b, Yb, out);

    cudaEventDestroy(evX);
    cudaEventDestroy(evE);
    cudaEventDestroy(evS1);
    cudaEventDestroy(evY);
    cudaStreamDestroy(s_aux);
}